// round 13
// baseline (speedup 1.0000x reference)
#include <cuda_runtime.h>
#include <cuda_fp16.h>
#include <math.h>

// Problem constants
#define B_    4
#define T_    2048
#define D_    1024
#define H_    16
#define HD_   64
#define FFN_  4096
#define ROWS_ (B_ * T_)        // 8192

// ---------------------------------------------------------------------------
// Scratch (device globals)
// ---------------------------------------------------------------------------
__device__ __half g_x [ROWS_ * D_];
__device__ __half g_q [ROWS_ * D_];
__device__ __half g_k [ROWS_ * D_];
__device__ __half g_v [ROWS_ * D_];
__device__ __half g_o [ROWS_ * D_];
__device__ float  g_h2[ROWS_ * D_];
__device__ __half g_y [ROWS_ * D_];
__device__ __half g_a [ROWS_ * FFN_];

// plain fp16 weights [k][n]
__device__ __half g_wq [D_ * D_];
__device__ __half g_wk [D_ * D_];
__device__ __half g_wv [D_ * D_];
__device__ __half g_wo [D_ * D_];
__device__ __half g_w1 [D_ * FFN_];
__device__ __half g_w2 [D_ * FFN_];
__device__ __half g_wout[FFN_ * D_];

// ---------------------------------------------------------------------------
// Helpers
// ---------------------------------------------------------------------------
__device__ __forceinline__ unsigned packh2(float lo, float hi) {
    __half2 h = __floats2half2_rn(lo, hi);
    return *reinterpret_cast<unsigned*>(&h);
}

__device__ __forceinline__ void mma_f16(float c[4],
                                        unsigned a0, unsigned a1, unsigned a2, unsigned a3,
                                        unsigned b0, unsigned b1) {
    asm volatile(
        "mma.sync.aligned.m16n8k16.row.col.f32.f16.f16.f32 "
        "{%0,%1,%2,%3}, {%4,%5,%6,%7}, {%8,%9}, {%0,%1,%2,%3};"
        : "+f"(c[0]), "+f"(c[1]), "+f"(c[2]), "+f"(c[3])
        : "r"(a0), "r"(a1), "r"(a2), "r"(a3), "r"(b0), "r"(b1));
}

__device__ __forceinline__ void ldm_x4(unsigned& r0, unsigned& r1,
                                       unsigned& r2, unsigned& r3, unsigned addr) {
    asm volatile("ldmatrix.sync.aligned.m8n8.x4.shared.b16 {%0,%1,%2,%3}, [%4];"
                 : "=r"(r0), "=r"(r1), "=r"(r2), "=r"(r3) : "r"(addr));
}

__device__ __forceinline__ void ldm_x4_trans(unsigned& r0, unsigned& r1,
                                             unsigned& r2, unsigned& r3, unsigned addr) {
    asm volatile("ldmatrix.sync.aligned.m8n8.x4.trans.shared.b16 {%0,%1,%2,%3}, [%4];"
                 : "=r"(r0), "=r"(r1), "=r"(r2), "=r"(r3) : "r"(addr));
}

__device__ __forceinline__ void cp16(unsigned dst, const void* src) {
    asm volatile("cp.async.cg.shared.global [%0], [%1], 16;" :: "r"(dst), "l"(src));
}
#define CP_COMMIT() asm volatile("cp.async.commit_group;" ::: "memory")
template <int N> __device__ __forceinline__ void cp_wait() {
    asm volatile("cp.async.wait_group %0;" :: "n"(N) : "memory");
}

// ---------------------------------------------------------------------------
// fp32 -> fp16 convert (weights)
// ---------------------------------------------------------------------------
__global__ void packh_kernel(const float* __restrict__ in, __half* __restrict__ out)
{
    int i = blockIdx.x * blockDim.x + threadIdx.x;
    float4 a = reinterpret_cast<const float4*>(in)[2 * i];
    float4 b = reinterpret_cast<const float4*>(in)[2 * i + 1];
    uint4 u;
    u.x = packh2(a.x, a.y); u.y = packh2(a.z, a.w);
    u.z = packh2(b.x, b.y); u.w = packh2(b.z, b.w);
    reinterpret_cast<uint4*>(out)[i] = u;
}

// ---------------------------------------------------------------------------
// LayerNorm: fp32 in, fp16 out
// ---------------------------------------------------------------------------
__global__ void ln_kernel(const float* __restrict__ in,
                          const float* __restrict__ gam,
                          const float* __restrict__ bet,
                          __half* __restrict__ out)
{
    __shared__ float r1[8], r2[8];
    __shared__ float s_mu, s_rstd;
    int row = blockIdx.x, tid = threadIdx.x;

    const float4* p = reinterpret_cast<const float4*>(in) + (size_t)row * (D_ / 4);
    float4 v = p[tid];
    float s  = v.x + v.y + v.z + v.w;
    float s2 = v.x * v.x + v.y * v.y + v.z * v.z + v.w * v.w;
    #pragma unroll
    for (int o = 16; o; o >>= 1) {
        s  += __shfl_xor_sync(0xffffffffu, s,  o);
        s2 += __shfl_xor_sync(0xffffffffu, s2, o);
    }
    if ((tid & 31) == 0) { r1[tid >> 5] = s; r2[tid >> 5] = s2; }
    __syncthreads();
    if (tid == 0) {
        float a = 0.f, b = 0.f;
        #pragma unroll
        for (int i = 0; i < 8; i++) { a += r1[i]; b += r2[i]; }
        float mu  = a / (float)D_;
        float var = b / (float)D_ - mu * mu;
        s_mu = mu;
        s_rstd = rsqrtf(var + 1e-5f);
    }
    __syncthreads();
    float mu = s_mu, rs = s_rstd;
    float4 g4 = reinterpret_cast<const float4*>(gam)[tid];
    float4 b4 = reinterpret_cast<const float4*>(bet)[tid];
    uint2 o;
    o.x = packh2((v.x - mu) * rs * g4.x + b4.x, (v.y - mu) * rs * g4.y + b4.y);
    o.y = packh2((v.z - mu) * rs * g4.z + b4.z, (v.w - mu) * rs * g4.w + b4.w);
    *reinterpret_cast<uint2*>(out + (size_t)row * D_ + tid * 4) = o;
}

// ---------------------------------------------------------------------------
// FP16 GEMM: C[M,N] = A[M,K] @ W[K,N] (+R). 256x128 tile, BK=32, 3-stage
// cp.async, 8 warps (4m x 2n), warp tile 64x64, mma.m16n8k16.
// A smem [m][k] stride 40 halfs (ldmatrix.x4); B smem [k][n] stride 136
// halfs (ldmatrix.x4.trans). Fragment-read redundancy halved vs 128x128.
// ---------------------------------------------------------------------------
#define ASTH_ 40                          // halfs per A row
#define BSTH_ 136                         // halfs per B row
#define ATILEH_ (256 * ASTH_)             // 10240 halfs / stage
#define BTILEH_ (32 * BSTH_)              // 4352 halfs / stage
#define GEMM_SMEM (3 * (ATILEH_ + BTILEH_) * 2)   // 87552 bytes

template <bool RES, bool OUT16, int NGEM>
__global__ void __launch_bounds__(256, 1)
tgemm_kernel(const __half* __restrict__ A,
             const __half* __restrict__ W0, const __half* __restrict__ W1,
             const __half* __restrict__ W2,
             const float* __restrict__ R,
             void* __restrict__ C0, void* __restrict__ C1, void* __restrict__ C2,
             int M, int N, int K)
{
    extern __shared__ char smraw[];
    __half* Ah = reinterpret_cast<__half*>(smraw);
    __half* Bh = reinterpret_cast<__half*>(smraw + 3 * ATILEH_ * 2);

    const __half* W = W0;
    void* C = C0;
    if (NGEM >= 2) {
        int z = blockIdx.z;
        W = (z == 0) ? W0 : (z == 1) ? W1 : W2;
        C = (z == 0) ? C0 : (z == 1) ? C1 : C2;
    }

    const int tid  = threadIdx.x;
    const int lane = tid & 31;
    const int warp = tid >> 5;
    const int wm   = (warp >> 1) * 64;    // 0,64,128,192
    const int wn   = (warp & 1) * 64;     // 0,64
    const int qk   = lane & 3;
    const int qm   = lane >> 2;

    const int bm = blockIdx.y * 256, bn = blockIdx.x * 128;

    const int lm_lo3  = lane & 7;
    const int lm_hi8  = (lane >> 3) & 1;
    const int lm_colh = lane >> 4;

    // staging: A one row per thread (4 x 16B chunks); B rows 0..31, 2 chunks each
    const int brow = tid >> 3;
    const int bch0 = (tid & 7) * 2;

    const __half* Abase = A + (size_t)bm * K;
    const __half* Wbase = W + bn;

    float acc[4][8][4];
    #pragma unroll
    for (int i = 0; i < 4; i++)
        #pragma unroll
        for (int j = 0; j < 8; j++)
            #pragma unroll
            for (int r = 0; r < 4; r++) acc[i][j][r] = 0.f;

    auto issue_tile = [&](int kt, int st) {
        unsigned abase = (unsigned)__cvta_generic_to_shared(&Ah[st * ATILEH_]);
        unsigned bbase = (unsigned)__cvta_generic_to_shared(&Bh[st * BTILEH_]);
        const __half* Ag = Abase + (size_t)tid * K + kt * 32;
        #pragma unroll
        for (int ch = 0; ch < 4; ch++)
            cp16(abase + (unsigned)(tid * ASTH_ + ch * 8) * 2, Ag + ch * 8);
        const __half* Bg = Wbase + (size_t)(kt * 32 + brow) * N;
        #pragma unroll
        for (int i = 0; i < 2; i++) {
            int ch = bch0 + i;
            cp16(bbase + (unsigned)(brow * BSTH_ + ch * 8) * 2, Bg + ch * 8);
        }
        CP_COMMIT();
    };

    const int ntiles = K / 32;

    issue_tile(0, 0);
    issue_tile(1, 1);
    cp_wait<1>();
    __syncthreads();

    for (int it = 0; it < ntiles; it++) {
        const int s = it % 3;
        if (it + 2 < ntiles) issue_tile(it + 2, (it + 2) % 3);

        unsigned asb = (unsigned)__cvta_generic_to_shared(&Ah[s * ATILEH_]);
        unsigned bsb = (unsigned)__cvta_generic_to_shared(&Bh[s * BTILEH_]);

        #pragma unroll
        for (int ks = 0; ks < 2; ks++) {
            const int kk = ks * 16;
            unsigned af[4][4];
            #pragma unroll
            for (int mf = 0; mf < 4; mf++) {
                int m = wm + mf * 16 + lm_hi8 * 8 + lm_lo3;
                unsigned addr = asb + (unsigned)(m * ASTH_ + kk + lm_colh * 8) * 2;
                ldm_x4(af[mf][0], af[mf][1], af[mf][2], af[mf][3], addr);
            }
            #pragma unroll
            for (int nb = 0; nb < 4; nb++) {
                int vrow = kk + lm_hi8 * 8 + lm_lo3;
                int vcol = wn + nb * 16 + lm_colh * 8;
                unsigned addr = bsb + (unsigned)(vrow * BSTH_ + vcol) * 2;
                unsigned b0, b1, b2, b3;
                ldm_x4_trans(b0, b1, b2, b3, addr);
                #pragma unroll
                for (int mf = 0; mf < 4; mf++) {
                    mma_f16(acc[mf][2 * nb],     af[mf][0], af[mf][1], af[mf][2], af[mf][3], b0, b1);
                    mma_f16(acc[mf][2 * nb + 1], af[mf][0], af[mf][1], af[mf][2], af[mf][3], b2, b3);
                }
            }
        }

        if (it + 2 < ntiles)       cp_wait<1>();
        else if (it + 1 < ntiles)  cp_wait<0>();
        __syncthreads();
    }

    #pragma unroll
    for (int mf = 0; mf < 4; mf++) {
        int row0 = bm + wm + mf * 16 + qm;
        #pragma unroll
        for (int nf = 0; nf < 8; nf++) {
            int col = bn + wn + nf * 8 + 2 * qk;
            size_t off0 = (size_t)row0 * N + col;
            size_t off1 = (size_t)(row0 + 8) * N + col;
            float c0 = acc[mf][nf][0], c1 = acc[mf][nf][1];
            float c2 = acc[mf][nf][2], c3 = acc[mf][nf][3];
            if (RES) {
                float2 r0 = *reinterpret_cast<const float2*>(R + off0);
                float2 r1 = *reinterpret_cast<const float2*>(R + off1);
                c0 += r0.x; c1 += r0.y;
                c2 += r1.x; c3 += r1.y;
            }
            if (OUT16) {
                __half* Ch = reinterpret_cast<__half*>(C);
                *reinterpret_cast<unsigned*>(Ch + off0) = packh2(c0, c1);
                *reinterpret_cast<unsigned*>(Ch + off1) = packh2(c2, c3);
            } else {
                float* Cf = reinterpret_cast<float*>(C);
                *reinterpret_cast<float2*>(Cf + off0) = make_float2(c0, c1);
                *reinterpret_cast<float2*>(Cf + off1) = make_float2(c2, c3);
            }
        }
    }
}

// ---------------------------------------------------------------------------
// Fused FFN (fp16): C = fp16(silu(A@W1) * (A@W2)). 256m x 64n per matrix,
// 8 warps (4m x 2n), warp tile 64x32 per matrix, dual accumulators.
// B smem = [k][ W1 cols 0..63 | W2 cols 64..127 ] stride 136 halfs.
// ---------------------------------------------------------------------------
__global__ void __launch_bounds__(256, 1)
ffn_kernel(const __half* __restrict__ A,
           const __half* __restrict__ W1h, const __half* __restrict__ W2h,
           __half* __restrict__ C, int M, int N, int K)
{
    extern __shared__ char smraw[];
    __half* Ah = reinterpret_cast<__half*>(smraw);
    __half* Bh = reinterpret_cast<__half*>(smraw + 3 * ATILEH_ * 2);

    const int tid  = threadIdx.x;
    const int lane = tid & 31;
    const int warp = tid >> 5;
    const int wm   = (warp >> 1) * 64;
    const int wn   = (warp & 1) * 32;
    const int qk   = lane & 3;
    const int qm   = lane >> 2;

    const int bm = blockIdx.y * 256, bn = blockIdx.x * 64;

    const int lm_lo3  = lane & 7;
    const int lm_hi8  = (lane >> 3) & 1;
    const int lm_colh = lane >> 4;

    const int brow = tid >> 3;
    const int bch0 = (tid & 7) * 2;

    const __half* Abase = A + (size_t)bm * K;

    float acc1[4][4][4], acc2[4][4][4];
    #pragma unroll
    for (int i = 0; i < 4; i++)
        #pragma unroll
        for (int j = 0; j < 4; j++)
            #pragma unroll
            for (int r = 0; r < 4; r++) { acc1[i][j][r] = 0.f; acc2[i][j][r] = 0.f; }

    auto issue_tile = [&](int kt, int st) {
        unsigned abase = (unsigned)__cvta_generic_to_shared(&Ah[st * ATILEH_]);
        unsigned bbase = (unsigned)__cvta_generic_to_shared(&Bh[st * BTILEH_]);
        const __half* Ag = Abase + (size_t)tid * K + kt * 32;
        #pragma unroll
        for (int ch = 0; ch < 4; ch++)
            cp16(abase + (unsigned)(tid * ASTH_ + ch * 8) * 2, Ag + ch * 8);
        #pragma unroll
        for (int i = 0; i < 2; i++) {
            int ch = bch0 + i;
            int colc = ch * 8;
            const __half* Bg = (colc < 64)
                ? (W1h + (size_t)(kt * 32 + brow) * N + bn + colc)
                : (W2h + (size_t)(kt * 32 + brow) * N + bn + colc - 64);
            cp16(bbase + (unsigned)(brow * BSTH_ + colc) * 2, Bg);
        }
        CP_COMMIT();
    };

    const int ntiles = K / 32;

    issue_tile(0, 0);
    issue_tile(1, 1);
    cp_wait<1>();
    __syncthreads();

    for (int it = 0; it < ntiles; it++) {
        const int s = it % 3;
        if (it + 2 < ntiles) issue_tile(it + 2, (it + 2) % 3);

        unsigned asb = (unsigned)__cvta_generic_to_shared(&Ah[s * ATILEH_]);
        unsigned bsb = (unsigned)__cvta_generic_to_shared(&Bh[s * BTILEH_]);

        #pragma unroll
        for (int ks = 0; ks < 2; ks++) {
            const int kk = ks * 16;
            unsigned af[4][4];
            #pragma unroll
            for (int mf = 0; mf < 4; mf++) {
                int m = wm + mf * 16 + lm_hi8 * 8 + lm_lo3;
                unsigned addr = asb + (unsigned)(m * ASTH_ + kk + lm_colh * 8) * 2;
                ldm_x4(af[mf][0], af[mf][1], af[mf][2], af[mf][3], addr);
            }
            #pragma unroll
            for (int nb = 0; nb < 2; nb++) {
                int vrow = kk + lm_hi8 * 8 + lm_lo3;
                int vcol1 = wn + nb * 16 + lm_colh * 8;
                unsigned a1_ = bsb + (unsigned)(vrow * BSTH_ + vcol1) * 2;
                unsigned a2_ = bsb + (unsigned)(vrow * BSTH_ + vcol1 + 64) * 2;
                unsigned b10, b11, b12, b13, b20, b21, b22, b23;
                ldm_x4_trans(b10, b11, b12, b13, a1_);
                ldm_x4_trans(b20, b21, b22, b23, a2_);
                #pragma unroll
                for (int mf = 0; mf < 4; mf++) {
                    mma_f16(acc1[mf][2 * nb],     af[mf][0], af[mf][1], af[mf][2], af[mf][3], b10, b11);
                    mma_f16(acc1[mf][2 * nb + 1], af[mf][0], af[mf][1], af[mf][2], af[mf][3], b12, b13);
                    mma_f16(acc2[mf][2 * nb],     af[mf][0], af[mf][1], af[mf][2], af[mf][3], b20, b21);
                    mma_f16(acc2[mf][2 * nb + 1], af[mf][0], af[mf][1], af[mf][2], af[mf][3], b22, b23);
                }
            }
        }

        if (it + 2 < ntiles)       cp_wait<1>();
        else if (it + 1 < ntiles)  cp_wait<0>();
        __syncthreads();
    }

    #pragma unroll
    for (int mf = 0; mf < 4; mf++) {
        int row0 = bm + wm + mf * 16 + qm;
        #pragma unroll
        for (int nf = 0; nf < 4; nf++) {
            int col = bn + wn + nf * 8 + 2 * qk;
            size_t off0 = (size_t)row0 * N + col;
            size_t off1 = (size_t)(row0 + 8) * N + col;
            float a0 = acc1[mf][nf][0], a1 = acc1[mf][nf][1];
            float a2 = acc1[mf][nf][2], a3 = acc1[mf][nf][3];
            float g0 = acc2[mf][nf][0], g1 = acc2[mf][nf][1];
            float g2 = acc2[mf][nf][2], g3 = acc2[mf][nf][3];
            *reinterpret_cast<unsigned*>(C + off0) =
                packh2(a0 / (1.f + __expf(-a0)) * g0, a1 / (1.f + __expf(-a1)) * g1);
            *reinterpret_cast<unsigned*>(C + off1) =
                packh2(a2 / (1.f + __expf(-a2)) * g2, a3 / (1.f + __expf(-a3)) * g3);
        }
    }
}

// ---------------------------------------------------------------------------
// Flash attention fp16 (unchanged; V via ldmatrix.trans)
// ---------------------------------------------------------------------------
#define STH_ 72
#define ATTN_SMEM ((64 * STH_ * 6) * 2 + 256 * 4)

__global__ void __launch_bounds__(256)
attn_kernel(const __half* __restrict__ Q, const __half* __restrict__ K,
            const __half* __restrict__ V, __half* __restrict__ O)
{
    extern __shared__ char smraw[];
    __half* Qs = reinterpret_cast<__half*>(smraw);
    __half* Ks = Qs + 64 * STH_;
    __half* Vs = Ks + 2 * 64 * STH_;
    __half* Ps = Vs + 2 * 64 * STH_;
    float* redmx = reinterpret_cast<float*>(Ps + 64 * STH_);
    float* redsm = redmx + 128;

    const int tid  = threadIdx.x;
    const int lane = tid & 31;
    const int warp = tid >> 5;
    const int wm   = (warp >> 1) * 16;
    const int wnh  = warp & 1;
    const int qm   = lane >> 2;
    const int qk   = lane & 3;

    const int b = blockIdx.y >> 4, h = blockIdx.y & 15;
    const int qi = gridDim.x - 1 - blockIdx.x;
    const int qb = qi * 64;

    const __half* Qb = Q + (size_t)b * T_ * D_ + h * HD_;
    const __half* Kb = K + (size_t)b * T_ * D_ + h * HD_;
    const __half* Vb = V + (size_t)b * T_ * D_ + h * HD_;

    const int lrow = tid >> 2, lch0 = (tid & 3) * 2;

    auto issue_kv = [&](int j, int s) {
        unsigned kb_ = (unsigned)__cvta_generic_to_shared(&Ks[s * 64 * STH_]);
        unsigned vb_ = (unsigned)__cvta_generic_to_shared(&Vs[s * 64 * STH_]);
        const __half* Kg = Kb + (size_t)(j * 64 + lrow) * D_;
        const __half* Vg = Vb + (size_t)(j * 64 + lrow) * D_;
        #pragma unroll
        for (int i = 0; i < 2; i++) {
            int ch = lch0 + i;
            cp16(kb_ + (unsigned)(lrow * STH_ + ch * 8) * 2, Kg + ch * 8);
            cp16(vb_ + (unsigned)(lrow * STH_ + ch * 8) * 2, Vg + ch * 8);
        }
        CP_COMMIT();
    };

    {
        unsigned qs_ = (unsigned)__cvta_generic_to_shared(Qs);
        const __half* Qg = Qb + (size_t)(qb + lrow) * D_;
        #pragma unroll
        for (int i = 0; i < 2; i++) {
            int ch = lch0 + i;
            cp16(qs_ + (unsigned)(lrow * STH_ + ch * 8) * 2, Qg + ch * 8);
        }
        CP_COMMIT();
    }
    issue_kv(0, 0);
    cp_wait<0>();
    __syncthreads();

    float acc[4][4];
    float m_i[2], l_i[2];
    m_i[0] = m_i[1] = -1e30f;
    l_i[0] = l_i[1] = 0.f;
    #pragma unroll
    for (int nf = 0; nf < 4; nf++)
        #pragma unroll
        for (int c = 0; c < 4; c++) acc[nf][c] = 0.f;

    const int r0l = wm + qm;
    const int ntile = qi + 1;

    const int lm_lo3  = lane & 7;
    const int lm_hi8  = (lane >> 3) & 1;
    const int lm_colh = lane >> 4;

    for (int j = 0; j < ntile; j++) {
        const int s = j & 1;
        if (j + 1 < ntile) issue_kv(j + 1, s ^ 1);

        const __half* Ksb = &Ks[s * 64 * STH_];
        const __half* Vsb = &Vs[s * 64 * STH_];
        unsigned vbase = (unsigned)__cvta_generic_to_shared(Vsb);

        float sv4[4][4];
        #pragma unroll
        for (int nf = 0; nf < 4; nf++)
            #pragma unroll
            for (int c = 0; c < 4; c++) sv4[nf][c] = 0.f;

        #pragma unroll
        for (int ks = 0; ks < 4; ks++) {
            const int kk = ks * 16;
            unsigned a0 = *reinterpret_cast<const unsigned*>(&Qs[(size_t)r0l * STH_ + kk + 2 * qk]);
            unsigned a1 = *reinterpret_cast<const unsigned*>(&Qs[(size_t)(r0l + 8) * STH_ + kk + 2 * qk]);
            unsigned a2 = *reinterpret_cast<const unsigned*>(&Qs[(size_t)r0l * STH_ + kk + 2 * qk + 8]);
            unsigned a3 = *reinterpret_cast<const unsigned*>(&Qs[(size_t)(r0l + 8) * STH_ + kk + 2 * qk + 8]);
            #pragma unroll
            for (int nf = 0; nf < 4; nf++) {
                int n = wnh * 32 + nf * 8 + qm;
                unsigned b0 = *reinterpret_cast<const unsigned*>(&Ksb[(size_t)n * STH_ + kk + 2 * qk]);
                unsigned b1 = *reinterpret_cast<const unsigned*>(&Ksb[(size_t)n * STH_ + kk + 2 * qk + 8]);
                mma_f16(sv4[nf], a0, a1, a2, a3, b0, b1);
            }
        }

        const bool diag = ((j * 64) == qb);
        #pragma unroll
        for (int nf = 0; nf < 4; nf++) {
            int colb = wnh * 32 + nf * 8 + 2 * qk;
            #pragma unroll
            for (int c = 0; c < 4; c++) {
                int col = colb + (c & 1);
                int row = r0l + ((c >> 1) ? 8 : 0);
                float sv = sv4[nf][c] * 0.125f;
                if (diag && (col > row)) sv = -1e30f;
                sv4[nf][c] = sv;
            }
        }

        float mx0 = -1e30f, mx1 = -1e30f;
        #pragma unroll
        for (int nf = 0; nf < 4; nf++) {
            mx0 = fmaxf(mx0, fmaxf(sv4[nf][0], sv4[nf][1]));
            mx1 = fmaxf(mx1, fmaxf(sv4[nf][2], sv4[nf][3]));
        }
        #pragma unroll
        for (int o = 1; o < 4; o <<= 1) {
            mx0 = fmaxf(mx0, __shfl_xor_sync(0xffffffffu, mx0, o));
            mx1 = fmaxf(mx1, __shfl_xor_sync(0xffffffffu, mx1, o));
        }
        if ((lane & 3) == 0) {
            redmx[wnh * 64 + r0l]     = mx0;
            redmx[wnh * 64 + r0l + 8] = mx1;
        }
        __syncthreads();
        float mn0 = fmaxf(m_i[0], fmaxf(redmx[r0l],     redmx[64 + r0l]));
        float mn1 = fmaxf(m_i[1], fmaxf(redmx[r0l + 8], redmx[64 + r0l + 8]));

        float sum0 = 0.f, sum1 = 0.f;
        #pragma unroll
        for (int nf = 0; nf < 4; nf++) {
            int colb = wnh * 32 + nf * 8 + 2 * qk;
            float p0 = __expf(sv4[nf][0] - mn0);
            float p1 = __expf(sv4[nf][1] - mn0);
            float p2 = __expf(sv4[nf][2] - mn1);
            float p3 = __expf(sv4[nf][3] - mn1);
            sum0 += p0 + p1;
            sum1 += p2 + p3;
            *reinterpret_cast<unsigned*>(&Ps[(size_t)r0l * STH_ + colb])       = packh2(p0, p1);
            *reinterpret_cast<unsigned*>(&Ps[(size_t)(r0l + 8) * STH_ + colb]) = packh2(p2, p3);
        }
        #pragma unroll
        for (int o = 1; o < 4; o <<= 1) {
            sum0 += __shfl_xor_sync(0xffffffffu, sum0, o);
            sum1 += __shfl_xor_sync(0xffffffffu, sum1, o);
        }
        if ((lane & 3) == 0) {
            redsm[wnh * 64 + r0l]     = sum0;
            redsm[wnh * 64 + r0l + 8] = sum1;
        }
        __syncthreads();
        float ts0 = redsm[r0l]     + redsm[64 + r0l];
        float ts1 = redsm[r0l + 8] + redsm[64 + r0l + 8];

        float al0 = __expf(m_i[0] - mn0);
        float al1 = __expf(m_i[1] - mn1);
        l_i[0] = l_i[0] * al0 + ts0;  m_i[0] = mn0;
        l_i[1] = l_i[1] * al1 + ts1;  m_i[1] = mn1;
        #pragma unroll
        for (int nf = 0; nf < 4; nf++) {
            acc[nf][0] *= al0; acc[nf][1] *= al0;
            acc[nf][2] *= al1; acc[nf][3] *= al1;
        }

        #pragma unroll
        for (int ks = 0; ks < 4; ks++) {
            const int kk = ks * 16;
            unsigned a0 = *reinterpret_cast<const unsigned*>(&Ps[(size_t)r0l * STH_ + kk + 2 * qk]);
            unsigned a1 = *reinterpret_cast<const unsigned*>(&Ps[(size_t)(r0l + 8) * STH_ + kk + 2 * qk]);
            unsigned a2 = *reinterpret_cast<const unsigned*>(&Ps[(size_t)r0l * STH_ + kk + 2 * qk + 8]);
            unsigned a3 = *reinterpret_cast<const unsigned*>(&Ps[(size_t)(r0l + 8) * STH_ + kk + 2 * qk + 8]);
            #pragma unroll
            for (int np = 0; np < 2; np++) {
                int n0 = wnh * 32 + np * 16;
                int vrow = kk + lm_hi8 * 8 + lm_lo3;
                int vcol = n0 + lm_colh * 8;
                unsigned addr = vbase + (unsigned)(vrow * STH_ + vcol) * 2;
                unsigned r0, r1, r2, r3;
                ldm_x4_trans(r0, r1, r2, r3, addr);
                mma_f16(acc[2 * np],     a0, a1, a2, a3, r0, r1);
                mma_f16(acc[2 * np + 1], a0, a1, a2, a3, r2, r3);
            }
        }

        if (j + 1 < ntile) cp_wait<0>();
        __syncthreads();
    }

    {
        float inv0 = 1.0f / l_i[0], inv1 = 1.0f / l_i[1];
        #pragma unroll
        for (int nf = 0; nf < 4; nf++) {
            int col = h * HD_ + wnh * 32 + nf * 8 + 2 * qk;
            size_t off0 = (size_t)b * T_ * D_ + (size_t)(qb + r0l) * D_ + col;
            size_t off1 = (size_t)b * T_ * D_ + (size_t)(qb + r0l + 8) * D_ + col;
            *reinterpret_cast<unsigned*>(O + off0) = packh2(acc[nf][0] * inv0, acc[nf][1] * inv0);
            *reinterpret_cast<unsigned*>(O + off1) = packh2(acc[nf][2] * inv1, acc[nf][3] * inv1);
        }
    }
}

// ---------------------------------------------------------------------------
// Orchestration
// ---------------------------------------------------------------------------
extern "C" void kernel_launch(void* const* d_in, const int* in_sizes, int n_in,
                              void* d_out, int out_size)
{
    const float* h    = (const float*)d_in[0];
    const float* alng = (const float*)d_in[2];
    const float* alnb = (const float*)d_in[3];
    const float* mlng = (const float*)d_in[4];
    const float* mlnb = (const float*)d_in[5];
    const float* wq   = (const float*)d_in[6];
    const float* wk   = (const float*)d_in[7];
    const float* wv   = (const float*)d_in[8];
    const float* wo   = (const float*)d_in[9];
    const float* w1   = (const float*)d_in[10];
    const float* w2   = (const float*)d_in[11];
    const float* wout = (const float*)d_in[12];
    float* out = (float*)d_out;

    __half *px, *pq, *pk, *pv, *po, *py, *pa;
    float *ph2;
    __half *pwq, *pwk, *pwv, *pwo, *pw1, *pw2, *pwout;
    cudaGetSymbolAddress((void**)&px,  g_x);
    cudaGetSymbolAddress((void**)&pq,  g_q);
    cudaGetSymbolAddress((void**)&pk,  g_k);
    cudaGetSymbolAddress((void**)&pv,  g_v);
    cudaGetSymbolAddress((void**)&po,  g_o);
    cudaGetSymbolAddress((void**)&ph2, g_h2);
    cudaGetSymbolAddress((void**)&py,  g_y);
    cudaGetSymbolAddress((void**)&pa,  g_a);
    cudaGetSymbolAddress((void**)&pwq,   g_wq);
    cudaGetSymbolAddress((void**)&pwk,   g_wk);
    cudaGetSymbolAddress((void**)&pwv,   g_wv);
    cudaGetSymbolAddress((void**)&pwo,   g_wo);
    cudaGetSymbolAddress((void**)&pw1,   g_w1);
    cudaGetSymbolAddress((void**)&pw2,   g_w2);
    cudaGetSymbolAddress((void**)&pwout, g_wout);

    cudaFuncSetAttribute(attn_kernel, cudaFuncAttributeMaxDynamicSharedMemorySize, ATTN_SMEM);
    cudaFuncSetAttribute(ffn_kernel,  cudaFuncAttributeMaxDynamicSharedMemorySize, GEMM_SMEM);
    cudaFuncSetAttribute(tgemm_kernel<false, true, 3>, cudaFuncAttributeMaxDynamicSharedMemorySize, GEMM_SMEM);
    cudaFuncSetAttribute(tgemm_kernel<true, false, 1>, cudaFuncAttributeMaxDynamicSharedMemorySize, GEMM_SMEM);

    // weights -> plain fp16
    packh_kernel<<<(D_ * D_ / 8) / 256, 256>>>(wq, pwq);
    packh_kernel<<<(D_ * D_ / 8) / 256, 256>>>(wk, pwk);
    packh_kernel<<<(D_ * D_ / 8) / 256, 256>>>(wv, pwv);
    packh_kernel<<<(D_ * D_ / 8) / 256, 256>>>(wo, pwo);
    packh_kernel<<<(D_ * FFN_ / 8) / 256, 256>>>(w1, pw1);
    packh_kernel<<<(D_ * FFN_ / 8) / 256, 256>>>(w2, pw2);
    packh_kernel<<<(FFN_ * D_ / 8) / 256, 256>>>(wout, pwout);

    dim3 gQKV(D_ / 128, ROWS_ / 256, 3);    // (8, 32, 3)
    dim3 gD(D_ / 128, ROWS_ / 256);         // (8, 32)
    dim3 gFFN(FFN_ / 64, ROWS_ / 256);      // (64, 32)

    // x = fp16(LN(h))
    ln_kernel<<<ROWS_, 256>>>(h, alng, alnb, px);
    // q,k,v = fp16(x @ {wq,wk,wv})
    tgemm_kernel<false, true, 3><<<gQKV, 256, GEMM_SMEM>>>(px, pwq, pwk, pwv, nullptr,
                                                           pq, pk, pv, ROWS_, D_, D_);
    // o = fp16(attention(q,k,v))
    attn_kernel<<<dim3(T_ / 64, B_ * H_), 256, ATTN_SMEM>>>(pq, pk, pv, po);
    // h2 = h + o @ wo   (fp32)
    tgemm_kernel<true, false, 1><<<gD, 256, GEMM_SMEM>>>(po, pwo, nullptr, nullptr, h,
                                                         ph2, nullptr, nullptr, ROWS_, D_, D_);
    // y = fp16(LN(h2))
    ln_kernel<<<ROWS_, 256>>>(ph2, mlng, mlnb, py);
    // a = fp16(silu(y@w1) * (y@w2))
    ffn_kernel<<<gFFN, 256, GEMM_SMEM>>>(py, pw1, pw2, pa, ROWS_, FFN_, D_);
    // out = h2 + a @ wout   (fp32)
    tgemm_kernel<true, false, 1><<<gD, 256, GEMM_SMEM>>>(pa, pwout, nullptr, nullptr, ph2,
                                                         out, nullptr, nullptr, ROWS_, D_, FFN_);
}

// round 14
// speedup vs baseline: 1.2455x; 1.2455x over previous
#include <cuda_runtime.h>
#include <cuda_fp16.h>
#include <math.h>

// Problem constants
#define B_    4
#define T_    2048
#define D_    1024
#define H_    16
#define HD_   64
#define FFN_  4096
#define ROWS_ (B_ * T_)        // 8192

// ---------------------------------------------------------------------------
// Scratch (device globals)
// ---------------------------------------------------------------------------
__device__ __half g_x [ROWS_ * D_];
__device__ __half g_q [ROWS_ * D_];
__device__ __half g_k [ROWS_ * D_];
__device__ __half g_v [ROWS_ * D_];
__device__ __half g_o [ROWS_ * D_];
__device__ float  g_h2[ROWS_ * D_];
__device__ __half g_y [ROWS_ * D_];
__device__ __half g_a [ROWS_ * FFN_];

// plain fp16 weights [k][n]
__device__ __half g_wq [D_ * D_];
__device__ __half g_wk [D_ * D_];
__device__ __half g_wv [D_ * D_];
__device__ __half g_wo [D_ * D_];
__device__ __half g_w1 [D_ * FFN_];
__device__ __half g_w2 [D_ * FFN_];
__device__ __half g_wout[FFN_ * D_];

// ---------------------------------------------------------------------------
// Helpers
// ---------------------------------------------------------------------------
__device__ __forceinline__ unsigned packh2(float lo, float hi) {
    __half2 h = __floats2half2_rn(lo, hi);
    return *reinterpret_cast<unsigned*>(&h);
}

__device__ __forceinline__ void mma_f16(float c[4],
                                        unsigned a0, unsigned a1, unsigned a2, unsigned a3,
                                        unsigned b0, unsigned b1) {
    asm volatile(
        "mma.sync.aligned.m16n8k16.row.col.f32.f16.f16.f32 "
        "{%0,%1,%2,%3}, {%4,%5,%6,%7}, {%8,%9}, {%0,%1,%2,%3};"
        : "+f"(c[0]), "+f"(c[1]), "+f"(c[2]), "+f"(c[3])
        : "r"(a0), "r"(a1), "r"(a2), "r"(a3), "r"(b0), "r"(b1));
}

__device__ __forceinline__ void ldm_x4(unsigned& r0, unsigned& r1,
                                       unsigned& r2, unsigned& r3, unsigned addr) {
    asm volatile("ldmatrix.sync.aligned.m8n8.x4.shared.b16 {%0,%1,%2,%3}, [%4];"
                 : "=r"(r0), "=r"(r1), "=r"(r2), "=r"(r3) : "r"(addr));
}

__device__ __forceinline__ void ldm_x4_trans(unsigned& r0, unsigned& r1,
                                             unsigned& r2, unsigned& r3, unsigned addr) {
    asm volatile("ldmatrix.sync.aligned.m8n8.x4.trans.shared.b16 {%0,%1,%2,%3}, [%4];"
                 : "=r"(r0), "=r"(r1), "=r"(r2), "=r"(r3) : "r"(addr));
}

__device__ __forceinline__ void cp16(unsigned dst, const void* src) {
    asm volatile("cp.async.cg.shared.global [%0], [%1], 16;" :: "r"(dst), "l"(src));
}
#define CP_COMMIT() asm volatile("cp.async.commit_group;" ::: "memory")
template <int N> __device__ __forceinline__ void cp_wait() {
    asm volatile("cp.async.wait_group %0;" :: "n"(N) : "memory");
}

// ---------------------------------------------------------------------------
// fp32 -> fp16 convert (weights); each thread handles 8 elements
// ---------------------------------------------------------------------------
__global__ void packh_kernel(const float* __restrict__ in, __half* __restrict__ out)
{
    int i = blockIdx.x * blockDim.x + threadIdx.x;
    float4 a = reinterpret_cast<const float4*>(in)[2 * i];
    float4 b = reinterpret_cast<const float4*>(in)[2 * i + 1];
    uint4 u;
    u.x = packh2(a.x, a.y); u.y = packh2(a.z, a.w);
    u.z = packh2(b.x, b.y); u.w = packh2(b.z, b.w);
    reinterpret_cast<uint4*>(out)[i] = u;
}

// ---------------------------------------------------------------------------
// LayerNorm: fp32 in, fp16 out
// ---------------------------------------------------------------------------
__global__ void ln_kernel(const float* __restrict__ in,
                          const float* __restrict__ gam,
                          const float* __restrict__ bet,
                          __half* __restrict__ out)
{
    __shared__ float r1[8], r2[8];
    __shared__ float s_mu, s_rstd;
    int row = blockIdx.x, tid = threadIdx.x;

    const float4* p = reinterpret_cast<const float4*>(in) + (size_t)row * (D_ / 4);
    float4 v = p[tid];
    float s  = v.x + v.y + v.z + v.w;
    float s2 = v.x * v.x + v.y * v.y + v.z * v.z + v.w * v.w;
    #pragma unroll
    for (int o = 16; o; o >>= 1) {
        s  += __shfl_xor_sync(0xffffffffu, s,  o);
        s2 += __shfl_xor_sync(0xffffffffu, s2, o);
    }
    if ((tid & 31) == 0) { r1[tid >> 5] = s; r2[tid >> 5] = s2; }
    __syncthreads();
    if (tid == 0) {
        float a = 0.f, b = 0.f;
        #pragma unroll
        for (int i = 0; i < 8; i++) { a += r1[i]; b += r2[i]; }
        float mu  = a / (float)D_;
        float var = b / (float)D_ - mu * mu;
        s_mu = mu;
        s_rstd = rsqrtf(var + 1e-5f);
    }
    __syncthreads();
    float mu = s_mu, rs = s_rstd;
    float4 g4 = reinterpret_cast<const float4*>(gam)[tid];
    float4 b4 = reinterpret_cast<const float4*>(bet)[tid];
    uint2 o;
    o.x = packh2((v.x - mu) * rs * g4.x + b4.x, (v.y - mu) * rs * g4.y + b4.y);
    o.y = packh2((v.z - mu) * rs * g4.z + b4.z, (v.w - mu) * rs * g4.w + b4.w);
    *reinterpret_cast<uint2*>(out + (size_t)row * D_ + tid * 4) = o;
}

// ---------------------------------------------------------------------------
// FP16 GEMM: C[M,N] = A[M,K] @ W[K,N] (+R). 128x128 tile, BK=32, 3-stage
// cp.async, 8 warps (4m x 2n), warp tile 32x64, mma.m16n8k16.
// A smem [m][k] stride 40 halfs, frags via ldmatrix.x4.
// B smem [k][n] stride 136 halfs, frags via ldmatrix.x4.trans.
// ---------------------------------------------------------------------------
#define ASTH_ 40                         // halfs per A row
#define BSTH_ 136                        // halfs per B row
#define ATILEH_ (128 * ASTH_)            // 5120 halfs / stage
#define BTILEH_ (32 * BSTH_)             // 4352 halfs / stage
#define GEMM_SMEM (3 * (ATILEH_ + BTILEH_) * 2)   // 56832 bytes

template <bool RES, bool OUT16, int NGEM>
__global__ void __launch_bounds__(256, 2)
tgemm_kernel(const __half* __restrict__ A,
             const __half* __restrict__ W0, const __half* __restrict__ W1,
             const __half* __restrict__ W2,
             const float* __restrict__ R,
             void* __restrict__ C0, void* __restrict__ C1, void* __restrict__ C2,
             int M, int N, int K)
{
    extern __shared__ char smraw[];
    __half* Ah = reinterpret_cast<__half*>(smraw);
    __half* Bh = reinterpret_cast<__half*>(smraw + 3 * ATILEH_ * 2);

    const __half* W = W0;
    void* C = C0;
    if (NGEM >= 2) {
        int z = blockIdx.z;
        W = (z == 0) ? W0 : (z == 1) ? W1 : W2;
        C = (z == 0) ? C0 : (z == 1) ? C1 : C2;
    }

    const int tid  = threadIdx.x;
    const int lane = tid & 31;
    const int warp = tid >> 5;
    const int wm   = (warp >> 1) * 32;
    const int wn   = (warp & 1) * 64;
    const int qk   = lane & 3;
    const int qm   = lane >> 2;

    const int bm = blockIdx.y * 128, bn = blockIdx.x * 128;

    // ldmatrix lane-address components
    const int lm_lo3  = lane & 7;
    const int lm_hi8  = (lane >> 3) & 1;
    const int lm_colh = lane >> 4;

    // staging: A rows 0..127 x 2 chunks of 16 halfs; B rows 0..31 x 16 chunks of 8 halfs
    const int arow = tid >> 1;
    const int ach0 = (tid & 1) * 2;
    const int brow = tid >> 3;
    const int bch0 = (tid & 7) * 2;

    const __half* Abase = A + (size_t)bm * K;
    const __half* Wbase = W + bn;

    float acc[2][8][4];
    #pragma unroll
    for (int i = 0; i < 2; i++)
        #pragma unroll
        for (int j = 0; j < 8; j++)
            #pragma unroll
            for (int r = 0; r < 4; r++) acc[i][j][r] = 0.f;

    auto issue_tile = [&](int kt, int st) {
        unsigned abase = (unsigned)__cvta_generic_to_shared(&Ah[st * ATILEH_]);
        unsigned bbase = (unsigned)__cvta_generic_to_shared(&Bh[st * BTILEH_]);
        const __half* Ag = Abase + (size_t)arow * K + kt * 32;
        #pragma unroll
        for (int i = 0; i < 2; i++) {
            int ch = ach0 + i;
            cp16(abase + (unsigned)(arow * ASTH_ + ch * 8) * 2, Ag + ch * 8);
        }
        const __half* Bg = Wbase + (size_t)(kt * 32 + brow) * N;
        #pragma unroll
        for (int i = 0; i < 2; i++) {
            int ch = bch0 + i;
            cp16(bbase + (unsigned)(brow * BSTH_ + ch * 8) * 2, Bg + ch * 8);
        }
        CP_COMMIT();
    };

    const int ntiles = K / 32;

    issue_tile(0, 0);
    issue_tile(1, 1);
    cp_wait<1>();
    __syncthreads();

    for (int it = 0; it < ntiles; it++) {
        const int s = it % 3;
        if (it + 2 < ntiles) issue_tile(it + 2, (it + 2) % 3);

        unsigned asb = (unsigned)__cvta_generic_to_shared(&Ah[s * ATILEH_]);
        unsigned bsb = (unsigned)__cvta_generic_to_shared(&Bh[s * BTILEH_]);

        #pragma unroll
        for (int ks = 0; ks < 2; ks++) {
            const int kk = ks * 16;
            unsigned af[2][4];
            #pragma unroll
            for (int mf = 0; mf < 2; mf++) {
                int m = wm + mf * 16 + lm_hi8 * 8 + lm_lo3;
                unsigned addr = asb + (unsigned)(m * ASTH_ + kk + lm_colh * 8) * 2;
                ldm_x4(af[mf][0], af[mf][1], af[mf][2], af[mf][3], addr);
            }
            #pragma unroll
            for (int nb = 0; nb < 4; nb++) {           // n16 blocks over 64
                int vrow = kk + lm_hi8 * 8 + lm_lo3;
                int vcol = wn + nb * 16 + lm_colh * 8;
                unsigned addr = bsb + (unsigned)(vrow * BSTH_ + vcol) * 2;
                unsigned b0, b1, b2, b3;
                ldm_x4_trans(b0, b1, b2, b3, addr);
                #pragma unroll
                for (int mf = 0; mf < 2; mf++) {
                    mma_f16(acc[mf][2 * nb],     af[mf][0], af[mf][1], af[mf][2], af[mf][3], b0, b1);
                    mma_f16(acc[mf][2 * nb + 1], af[mf][0], af[mf][1], af[mf][2], af[mf][3], b2, b3);
                }
            }
        }

        if (it + 2 < ntiles)       cp_wait<1>();
        else if (it + 1 < ntiles)  cp_wait<0>();
        __syncthreads();
    }

    #pragma unroll
    for (int mf = 0; mf < 2; mf++) {
        int row0 = bm + wm + mf * 16 + qm;
        #pragma unroll
        for (int nf = 0; nf < 8; nf++) {
            int col = bn + wn + nf * 8 + 2 * qk;
            size_t off0 = (size_t)row0 * N + col;
            size_t off1 = (size_t)(row0 + 8) * N + col;
            float c0 = acc[mf][nf][0], c1 = acc[mf][nf][1];
            float c2 = acc[mf][nf][2], c3 = acc[mf][nf][3];
            if (RES) {
                float2 r0 = *reinterpret_cast<const float2*>(R + off0);
                float2 r1 = *reinterpret_cast<const float2*>(R + off1);
                c0 += r0.x; c1 += r0.y;
                c2 += r1.x; c3 += r1.y;
            }
            if (OUT16) {
                __half* Ch = reinterpret_cast<__half*>(C);
                *reinterpret_cast<unsigned*>(Ch + off0) = packh2(c0, c1);
                *reinterpret_cast<unsigned*>(Ch + off1) = packh2(c2, c3);
            } else {
                float* Cf = reinterpret_cast<float*>(C);
                *reinterpret_cast<float2*>(Cf + off0) = make_float2(c0, c1);
                *reinterpret_cast<float2*>(Cf + off1) = make_float2(c2, c3);
            }
        }
    }
}

// ---------------------------------------------------------------------------
// Fused FFN (fp16): C = fp16(silu(A@W1) * (A@W2)). 128m x 64n per matrix,
// 8 warps (4m x 2n), warp tile 32x32 per matrix, dual accumulators.
// B smem = [k][ W1 cols 0..63 | W2 cols 64..127 ] stride 136 halfs.
// ---------------------------------------------------------------------------
__global__ void __launch_bounds__(256, 2)
ffn_kernel(const __half* __restrict__ A,
           const __half* __restrict__ W1h, const __half* __restrict__ W2h,
           __half* __restrict__ C, int M, int N, int K)
{
    extern __shared__ char smraw[];
    __half* Ah = reinterpret_cast<__half*>(smraw);
    __half* Bh = reinterpret_cast<__half*>(smraw + 3 * ATILEH_ * 2);

    const int tid  = threadIdx.x;
    const int lane = tid & 31;
    const int warp = tid >> 5;
    const int wm   = (warp >> 1) * 32;
    const int wn   = (warp & 1) * 32;
    const int qk   = lane & 3;
    const int qm   = lane >> 2;

    const int bm = blockIdx.y * 128, bn = blockIdx.x * 64;

    const int lm_lo3  = lane & 7;
    const int lm_hi8  = (lane >> 3) & 1;
    const int lm_colh = lane >> 4;

    const int arow = tid >> 1;
    const int ach0 = (tid & 1) * 2;
    const int brow = tid >> 3;
    const int bch0 = (tid & 7) * 2;

    const __half* Abase = A + (size_t)bm * K;

    float acc1[2][4][4], acc2[2][4][4];
    #pragma unroll
    for (int i = 0; i < 2; i++)
        #pragma unroll
        for (int j = 0; j < 4; j++)
            #pragma unroll
            for (int r = 0; r < 4; r++) { acc1[i][j][r] = 0.f; acc2[i][j][r] = 0.f; }

    auto issue_tile = [&](int kt, int st) {
        unsigned abase = (unsigned)__cvta_generic_to_shared(&Ah[st * ATILEH_]);
        unsigned bbase = (unsigned)__cvta_generic_to_shared(&Bh[st * BTILEH_]);
        const __half* Ag = Abase + (size_t)arow * K + kt * 32;
        #pragma unroll
        for (int i = 0; i < 2; i++) {
            int ch = ach0 + i;
            cp16(abase + (unsigned)(arow * ASTH_ + ch * 8) * 2, Ag + ch * 8);
        }
        #pragma unroll
        for (int i = 0; i < 2; i++) {
            int ch = bch0 + i;                  // 0..15; cols ch*8..ch*8+7
            int colc = ch * 8;
            const __half* Bg = (colc < 64)
                ? (W1h + (size_t)(kt * 32 + brow) * N + bn + colc)
                : (W2h + (size_t)(kt * 32 + brow) * N + bn + colc - 64);
            cp16(bbase + (unsigned)(brow * BSTH_ + colc) * 2, Bg);
        }
        CP_COMMIT();
    };

    const int ntiles = K / 32;

    issue_tile(0, 0);
    issue_tile(1, 1);
    cp_wait<1>();
    __syncthreads();

    for (int it = 0; it < ntiles; it++) {
        const int s = it % 3;
        if (it + 2 < ntiles) issue_tile(it + 2, (it + 2) % 3);

        unsigned asb = (unsigned)__cvta_generic_to_shared(&Ah[s * ATILEH_]);
        unsigned bsb = (unsigned)__cvta_generic_to_shared(&Bh[s * BTILEH_]);

        #pragma unroll
        for (int ks = 0; ks < 2; ks++) {
            const int kk = ks * 16;
            unsigned af[2][4];
            #pragma unroll
            for (int mf = 0; mf < 2; mf++) {
                int m = wm + mf * 16 + lm_hi8 * 8 + lm_lo3;
                unsigned addr = asb + (unsigned)(m * ASTH_ + kk + lm_colh * 8) * 2;
                ldm_x4(af[mf][0], af[mf][1], af[mf][2], af[mf][3], addr);
            }
            #pragma unroll
            for (int nb = 0; nb < 2; nb++) {          // n16 blocks over 32
                int vrow = kk + lm_hi8 * 8 + lm_lo3;
                int vcol1 = wn + nb * 16 + lm_colh * 8;
                unsigned a1_ = bsb + (unsigned)(vrow * BSTH_ + vcol1) * 2;
                unsigned a2_ = bsb + (unsigned)(vrow * BSTH_ + vcol1 + 64) * 2;
                unsigned b10, b11, b12, b13, b20, b21, b22, b23;
                ldm_x4_trans(b10, b11, b12, b13, a1_);
                ldm_x4_trans(b20, b21, b22, b23, a2_);
                #pragma unroll
                for (int mf = 0; mf < 2; mf++) {
                    mma_f16(acc1[mf][2 * nb],     af[mf][0], af[mf][1], af[mf][2], af[mf][3], b10, b11);
                    mma_f16(acc1[mf][2 * nb + 1], af[mf][0], af[mf][1], af[mf][2], af[mf][3], b12, b13);
                    mma_f16(acc2[mf][2 * nb],     af[mf][0], af[mf][1], af[mf][2], af[mf][3], b20, b21);
                    mma_f16(acc2[mf][2 * nb + 1], af[mf][0], af[mf][1], af[mf][2], af[mf][3], b22, b23);
                }
            }
        }

        if (it + 2 < ntiles)       cp_wait<1>();
        else if (it + 1 < ntiles)  cp_wait<0>();
        __syncthreads();
    }

    #pragma unroll
    for (int mf = 0; mf < 2; mf++) {
        int row0 = bm + wm + mf * 16 + qm;
        #pragma unroll
        for (int nf = 0; nf < 4; nf++) {
            int col = bn + wn + nf * 8 + 2 * qk;
            size_t off0 = (size_t)row0 * N + col;
            size_t off1 = (size_t)(row0 + 8) * N + col;
            float a0 = acc1[mf][nf][0], a1 = acc1[mf][nf][1];
            float a2 = acc1[mf][nf][2], a3 = acc1[mf][nf][3];
            float g0 = acc2[mf][nf][0], g1 = acc2[mf][nf][1];
            float g2 = acc2[mf][nf][2], g3 = acc2[mf][nf][3];
            *reinterpret_cast<unsigned*>(C + off0) =
                packh2(a0 / (1.f + __expf(-a0)) * g0, a1 / (1.f + __expf(-a1)) * g1);
            *reinterpret_cast<unsigned*>(C + off1) =
                packh2(a2 / (1.f + __expf(-a2)) * g2, a3 / (1.f + __expf(-a3)) * g3);
        }
    }
}

// ---------------------------------------------------------------------------
// Flash attention fp16 (V via ldmatrix.trans), now 2 CTAs/SM.
// ---------------------------------------------------------------------------
#define STH_ 72
#define ATTN_SMEM ((64 * STH_ * 6) * 2 + 256 * 4)

__global__ void __launch_bounds__(256, 2)
attn_kernel(const __half* __restrict__ Q, const __half* __restrict__ K,
            const __half* __restrict__ V, __half* __restrict__ O)
{
    extern __shared__ char smraw[];
    __half* Qs = reinterpret_cast<__half*>(smraw);
    __half* Ks = Qs + 64 * STH_;
    __half* Vs = Ks + 2 * 64 * STH_;
    __half* Ps = Vs + 2 * 64 * STH_;
    float* redmx = reinterpret_cast<float*>(Ps + 64 * STH_);
    float* redsm = redmx + 128;

    const int tid  = threadIdx.x;
    const int lane = tid & 31;
    const int warp = tid >> 5;
    const int wm   = (warp >> 1) * 16;
    const int wnh  = warp & 1;
    const int qm   = lane >> 2;
    const int qk   = lane & 3;

    const int b = blockIdx.y >> 4, h = blockIdx.y & 15;
    const int qi = gridDim.x - 1 - blockIdx.x;
    const int qb = qi * 64;

    const __half* Qb = Q + (size_t)b * T_ * D_ + h * HD_;
    const __half* Kb = K + (size_t)b * T_ * D_ + h * HD_;
    const __half* Vb = V + (size_t)b * T_ * D_ + h * HD_;

    const int lrow = tid >> 2, lch0 = (tid & 3) * 2;

    auto issue_kv = [&](int j, int s) {
        unsigned kb_ = (unsigned)__cvta_generic_to_shared(&Ks[s * 64 * STH_]);
        unsigned vb_ = (unsigned)__cvta_generic_to_shared(&Vs[s * 64 * STH_]);
        const __half* Kg = Kb + (size_t)(j * 64 + lrow) * D_;
        const __half* Vg = Vb + (size_t)(j * 64 + lrow) * D_;
        #pragma unroll
        for (int i = 0; i < 2; i++) {
            int ch = lch0 + i;
            cp16(kb_ + (unsigned)(lrow * STH_ + ch * 8) * 2, Kg + ch * 8);
            cp16(vb_ + (unsigned)(lrow * STH_ + ch * 8) * 2, Vg + ch * 8);
        }
        CP_COMMIT();
    };

    {
        unsigned qs_ = (unsigned)__cvta_generic_to_shared(Qs);
        const __half* Qg = Qb + (size_t)(qb + lrow) * D_;
        #pragma unroll
        for (int i = 0; i < 2; i++) {
            int ch = lch0 + i;
            cp16(qs_ + (unsigned)(lrow * STH_ + ch * 8) * 2, Qg + ch * 8);
        }
        CP_COMMIT();
    }
    issue_kv(0, 0);
    cp_wait<0>();
    __syncthreads();

    float acc[4][4];
    float m_i[2], l_i[2];
    m_i[0] = m_i[1] = -1e30f;
    l_i[0] = l_i[1] = 0.f;
    #pragma unroll
    for (int nf = 0; nf < 4; nf++)
        #pragma unroll
        for (int c = 0; c < 4; c++) acc[nf][c] = 0.f;

    const int r0l = wm + qm;
    const int ntile = qi + 1;

    const int lm_lo3  = lane & 7;
    const int lm_hi8  = (lane >> 3) & 1;
    const int lm_colh = lane >> 4;

    for (int j = 0; j < ntile; j++) {
        const int s = j & 1;
        if (j + 1 < ntile) issue_kv(j + 1, s ^ 1);

        const __half* Ksb = &Ks[s * 64 * STH_];
        const __half* Vsb = &Vs[s * 64 * STH_];
        unsigned vbase = (unsigned)__cvta_generic_to_shared(Vsb);

        float sv4[4][4];
        #pragma unroll
        for (int nf = 0; nf < 4; nf++)
            #pragma unroll
            for (int c = 0; c < 4; c++) sv4[nf][c] = 0.f;

        #pragma unroll
        for (int ks = 0; ks < 4; ks++) {
            const int kk = ks * 16;
            unsigned a0 = *reinterpret_cast<const unsigned*>(&Qs[(size_t)r0l * STH_ + kk + 2 * qk]);
            unsigned a1 = *reinterpret_cast<const unsigned*>(&Qs[(size_t)(r0l + 8) * STH_ + kk + 2 * qk]);
            unsigned a2 = *reinterpret_cast<const unsigned*>(&Qs[(size_t)r0l * STH_ + kk + 2 * qk + 8]);
            unsigned a3 = *reinterpret_cast<const unsigned*>(&Qs[(size_t)(r0l + 8) * STH_ + kk + 2 * qk + 8]);
            #pragma unroll
            for (int nf = 0; nf < 4; nf++) {
                int n = wnh * 32 + nf * 8 + qm;
                unsigned b0 = *reinterpret_cast<const unsigned*>(&Ksb[(size_t)n * STH_ + kk + 2 * qk]);
                unsigned b1 = *reinterpret_cast<const unsigned*>(&Ksb[(size_t)n * STH_ + kk + 2 * qk + 8]);
                mma_f16(sv4[nf], a0, a1, a2, a3, b0, b1);
            }
        }

        const bool diag = ((j * 64) == qb);
        #pragma unroll
        for (int nf = 0; nf < 4; nf++) {
            int colb = wnh * 32 + nf * 8 + 2 * qk;
            #pragma unroll
            for (int c = 0; c < 4; c++) {
                int col = colb + (c & 1);
                int row = r0l + ((c >> 1) ? 8 : 0);
                float sv = sv4[nf][c] * 0.125f;
                if (diag && (col > row)) sv = -1e30f;
                sv4[nf][c] = sv;
            }
        }

        float mx0 = -1e30f, mx1 = -1e30f;
        #pragma unroll
        for (int nf = 0; nf < 4; nf++) {
            mx0 = fmaxf(mx0, fmaxf(sv4[nf][0], sv4[nf][1]));
            mx1 = fmaxf(mx1, fmaxf(sv4[nf][2], sv4[nf][3]));
        }
        #pragma unroll
        for (int o = 1; o < 4; o <<= 1) {
            mx0 = fmaxf(mx0, __shfl_xor_sync(0xffffffffu, mx0, o));
            mx1 = fmaxf(mx1, __shfl_xor_sync(0xffffffffu, mx1, o));
        }
        if ((lane & 3) == 0) {
            redmx[wnh * 64 + r0l]     = mx0;
            redmx[wnh * 64 + r0l + 8] = mx1;
        }
        __syncthreads();
        float mn0 = fmaxf(m_i[0], fmaxf(redmx[r0l],     redmx[64 + r0l]));
        float mn1 = fmaxf(m_i[1], fmaxf(redmx[r0l + 8], redmx[64 + r0l + 8]));

        float sum0 = 0.f, sum1 = 0.f;
        #pragma unroll
        for (int nf = 0; nf < 4; nf++) {
            int colb = wnh * 32 + nf * 8 + 2 * qk;
            float p0 = __expf(sv4[nf][0] - mn0);
            float p1 = __expf(sv4[nf][1] - mn0);
            float p2 = __expf(sv4[nf][2] - mn1);
            float p3 = __expf(sv4[nf][3] - mn1);
            sum0 += p0 + p1;
            sum1 += p2 + p3;
            *reinterpret_cast<unsigned*>(&Ps[(size_t)r0l * STH_ + colb])       = packh2(p0, p1);
            *reinterpret_cast<unsigned*>(&Ps[(size_t)(r0l + 8) * STH_ + colb]) = packh2(p2, p3);
        }
        #pragma unroll
        for (int o = 1; o < 4; o <<= 1) {
            sum0 += __shfl_xor_sync(0xffffffffu, sum0, o);
            sum1 += __shfl_xor_sync(0xffffffffu, sum1, o);
        }
        if ((lane & 3) == 0) {
            redsm[wnh * 64 + r0l]     = sum0;
            redsm[wnh * 64 + r0l + 8] = sum1;
        }
        __syncthreads();
        float ts0 = redsm[r0l]     + redsm[64 + r0l];
        float ts1 = redsm[r0l + 8] + redsm[64 + r0l + 8];

        float al0 = __expf(m_i[0] - mn0);
        float al1 = __expf(m_i[1] - mn1);
        l_i[0] = l_i[0] * al0 + ts0;  m_i[0] = mn0;
        l_i[1] = l_i[1] * al1 + ts1;  m_i[1] = mn1;
        #pragma unroll
        for (int nf = 0; nf < 4; nf++) {
            acc[nf][0] *= al0; acc[nf][1] *= al0;
            acc[nf][2] *= al1; acc[nf][3] *= al1;
        }

        #pragma unroll
        for (int ks = 0; ks < 4; ks++) {
            const int kk = ks * 16;
            unsigned a0 = *reinterpret_cast<const unsigned*>(&Ps[(size_t)r0l * STH_ + kk + 2 * qk]);
            unsigned a1 = *reinterpret_cast<const unsigned*>(&Ps[(size_t)(r0l + 8) * STH_ + kk + 2 * qk]);
            unsigned a2 = *reinterpret_cast<const unsigned*>(&Ps[(size_t)r0l * STH_ + kk + 2 * qk + 8]);
            unsigned a3 = *reinterpret_cast<const unsigned*>(&Ps[(size_t)(r0l + 8) * STH_ + kk + 2 * qk + 8]);
            #pragma unroll
            for (int np = 0; np < 2; np++) {
                int n0 = wnh * 32 + np * 16;
                int vrow = kk + lm_hi8 * 8 + lm_lo3;
                int vcol = n0 + lm_colh * 8;
                unsigned addr = vbase + (unsigned)(vrow * STH_ + vcol) * 2;
                unsigned r0, r1, r2, r3;
                ldm_x4_trans(r0, r1, r2, r3, addr);
                mma_f16(acc[2 * np],     a0, a1, a2, a3, r0, r1);
                mma_f16(acc[2 * np + 1], a0, a1, a2, a3, r2, r3);
            }
        }

        if (j + 1 < ntile) cp_wait<0>();
        __syncthreads();
    }

    {
        float inv0 = 1.0f / l_i[0], inv1 = 1.0f / l_i[1];
        #pragma unroll
        for (int nf = 0; nf < 4; nf++) {
            int col = h * HD_ + wnh * 32 + nf * 8 + 2 * qk;
            size_t off0 = (size_t)b * T_ * D_ + (size_t)(qb + r0l) * D_ + col;
            size_t off1 = (size_t)b * T_ * D_ + (size_t)(qb + r0l + 8) * D_ + col;
            *reinterpret_cast<unsigned*>(O + off0) = packh2(acc[nf][0] * inv0, acc[nf][1] * inv0);
            *reinterpret_cast<unsigned*>(O + off1) = packh2(acc[nf][2] * inv1, acc[nf][3] * inv1);
        }
    }
}

// ---------------------------------------------------------------------------
// Orchestration
// ---------------------------------------------------------------------------
extern "C" void kernel_launch(void* const* d_in, const int* in_sizes, int n_in,
                              void* d_out, int out_size)
{
    const float* h    = (const float*)d_in[0];
    const float* alng = (const float*)d_in[2];
    const float* alnb = (const float*)d_in[3];
    const float* mlng = (const float*)d_in[4];
    const float* mlnb = (const float*)d_in[5];
    const float* wq   = (const float*)d_in[6];
    const float* wk   = (const float*)d_in[7];
    const float* wv   = (const float*)d_in[8];
    const float* wo   = (const float*)d_in[9];
    const float* w1   = (const float*)d_in[10];
    const float* w2   = (const float*)d_in[11];
    const float* wout = (const float*)d_in[12];
    float* out = (float*)d_out;

    __half *px, *pq, *pk, *pv, *po, *py, *pa;
    float *ph2;
    __half *pwq, *pwk, *pwv, *pwo, *pw1, *pw2, *pwout;
    cudaGetSymbolAddress((void**)&px,  g_x);
    cudaGetSymbolAddress((void**)&pq,  g_q);
    cudaGetSymbolAddress((void**)&pk,  g_k);
    cudaGetSymbolAddress((void**)&pv,  g_v);
    cudaGetSymbolAddress((void**)&po,  g_o);
    cudaGetSymbolAddress((void**)&ph2, g_h2);
    cudaGetSymbolAddress((void**)&py,  g_y);
    cudaGetSymbolAddress((void**)&pa,  g_a);
    cudaGetSymbolAddress((void**)&pwq,   g_wq);
    cudaGetSymbolAddress((void**)&pwk,   g_wk);
    cudaGetSymbolAddress((void**)&pwv,   g_wv);
    cudaGetSymbolAddress((void**)&pwo,   g_wo);
    cudaGetSymbolAddress((void**)&pw1,   g_w1);
    cudaGetSymbolAddress((void**)&pw2,   g_w2);
    cudaGetSymbolAddress((void**)&pwout, g_wout);

    cudaFuncSetAttribute(attn_kernel, cudaFuncAttributeMaxDynamicSharedMemorySize, ATTN_SMEM);
    cudaFuncSetAttribute(ffn_kernel,  cudaFuncAttributeMaxDynamicSharedMemorySize, GEMM_SMEM);
    cudaFuncSetAttribute(tgemm_kernel<false, true, 3>, cudaFuncAttributeMaxDynamicSharedMemorySize, GEMM_SMEM);
    cudaFuncSetAttribute(tgemm_kernel<true, false, 1>, cudaFuncAttributeMaxDynamicSharedMemorySize, GEMM_SMEM);

    // weights -> plain fp16
    packh_kernel<<<(D_ * D_ / 8) / 256, 256>>>(wq, pwq);
    packh_kernel<<<(D_ * D_ / 8) / 256, 256>>>(wk, pwk);
    packh_kernel<<<(D_ * D_ / 8) / 256, 256>>>(wv, pwv);
    packh_kernel<<<(D_ * D_ / 8) / 256, 256>>>(wo, pwo);
    packh_kernel<<<(D_ * FFN_ / 8) / 256, 256>>>(w1, pw1);
    packh_kernel<<<(D_ * FFN_ / 8) / 256, 256>>>(w2, pw2);
    packh_kernel<<<(FFN_ * D_ / 8) / 256, 256>>>(wout, pwout);

    dim3 gQKV(D_ / 128, ROWS_ / 128, 3);    // (8, 64, 3)
    dim3 gD(D_ / 128, ROWS_ / 128);         // (8, 64)
    dim3 gFFN(FFN_ / 64, ROWS_ / 128);      // (64, 64)

    // x = fp16(LN(h))
    ln_kernel<<<ROWS_, 256>>>(h, alng, alnb, px);
    // q,k,v = fp16(x @ {wq,wk,wv})
    tgemm_kernel<false, true, 3><<<gQKV, 256, GEMM_SMEM>>>(px, pwq, pwk, pwv, nullptr,
                                                           pq, pk, pv, ROWS_, D_, D_);
    // o = fp16(attention(q,k,v))
    attn_kernel<<<dim3(T_ / 64, B_ * H_), 256, ATTN_SMEM>>>(pq, pk, pv, po);
    // h2 = h + o @ wo   (fp32)
    tgemm_kernel<true, false, 1><<<gD, 256, GEMM_SMEM>>>(po, pwo, nullptr, nullptr, h,
                                                         ph2, nullptr, nullptr, ROWS_, D_, D_);
    // y = fp16(LN(h2))
    ln_kernel<<<ROWS_, 256>>>(ph2, mlng, mlnb, py);
    // a = fp16(silu(y@w1) * (y@w2))
    ffn_kernel<<<gFFN, 256, GEMM_SMEM>>>(py, pw1, pw2, pa, ROWS_, FFN_, D_);
    // out = h2 + a @ wout   (fp32)
    tgemm_kernel<true, false, 1><<<gD, 256, GEMM_SMEM>>>(pa, pwout, nullptr, nullptr, ph2,
                                                         out, nullptr, nullptr, ROWS_, D_, FFN_);
}

// round 15
// speedup vs baseline: 1.2535x; 1.0064x over previous
#include <cuda_runtime.h>
#include <cuda_fp16.h>
#include <math.h>

// Problem constants
#define B_    4
#define T_    2048
#define D_    1024
#define H_    16
#define HD_   64
#define FFN_  4096
#define ROWS_ (B_ * T_)        // 8192

// ---------------------------------------------------------------------------
// Scratch (device globals)
// ---------------------------------------------------------------------------
__device__ __half g_x [ROWS_ * D_];
__device__ __half g_q [ROWS_ * D_];
__device__ __half g_k [ROWS_ * D_];
__device__ __half g_v [ROWS_ * D_];
__device__ __half g_o [ROWS_ * D_];
__device__ float  g_h2[ROWS_ * D_];
__device__ __half g_y [ROWS_ * D_];
__device__ __half g_a [ROWS_ * FFN_];

// plain fp16 weights [k][n]
__device__ __half g_wq [D_ * D_];
__device__ __half g_wk [D_ * D_];
__device__ __half g_wv [D_ * D_];
__device__ __half g_wo [D_ * D_];
__device__ __half g_w1 [D_ * FFN_];
__device__ __half g_w2 [D_ * FFN_];
__device__ __half g_wout[FFN_ * D_];

// ---------------------------------------------------------------------------
// Helpers
// ---------------------------------------------------------------------------
__device__ __forceinline__ unsigned packh2(float lo, float hi) {
    __half2 h = __floats2half2_rn(lo, hi);
    return *reinterpret_cast<unsigned*>(&h);
}

__device__ __forceinline__ void mma_f16(float c[4],
                                        unsigned a0, unsigned a1, unsigned a2, unsigned a3,
                                        unsigned b0, unsigned b1) {
    asm volatile(
        "mma.sync.aligned.m16n8k16.row.col.f32.f16.f16.f32 "
        "{%0,%1,%2,%3}, {%4,%5,%6,%7}, {%8,%9}, {%0,%1,%2,%3};"
        : "+f"(c[0]), "+f"(c[1]), "+f"(c[2]), "+f"(c[3])
        : "r"(a0), "r"(a1), "r"(a2), "r"(a3), "r"(b0), "r"(b1));
}

__device__ __forceinline__ void ldm_x4(unsigned& r0, unsigned& r1,
                                       unsigned& r2, unsigned& r3, unsigned addr) {
    asm volatile("ldmatrix.sync.aligned.m8n8.x4.shared.b16 {%0,%1,%2,%3}, [%4];"
                 : "=r"(r0), "=r"(r1), "=r"(r2), "=r"(r3) : "r"(addr));
}

__device__ __forceinline__ void ldm_x4_trans(unsigned& r0, unsigned& r1,
                                             unsigned& r2, unsigned& r3, unsigned addr) {
    asm volatile("ldmatrix.sync.aligned.m8n8.x4.trans.shared.b16 {%0,%1,%2,%3}, [%4];"
                 : "=r"(r0), "=r"(r1), "=r"(r2), "=r"(r3) : "r"(addr));
}

__device__ __forceinline__ void cp16(unsigned dst, const void* src) {
    asm volatile("cp.async.cg.shared.global [%0], [%1], 16;" :: "r"(dst), "l"(src));
}
#define CP_COMMIT() asm volatile("cp.async.commit_group;" ::: "memory")
template <int N> __device__ __forceinline__ void cp_wait() {
    asm volatile("cp.async.wait_group %0;" :: "n"(N) : "memory");
}

// ---------------------------------------------------------------------------
// Fused fp32 -> fp16 conversion for ALL weights in one launch.
// Each thread converts 8 elements. Segments in units of 8 elements:
//   wq,wk,wv,wo: 131072 each; w1,w2: 524288; wout: 524288. Total 2097152.
// ---------------------------------------------------------------------------
struct PackArgs {
    const float* src[7];
    __half*      dst[7];
};

__global__ void packall_kernel(PackArgs pa)
{
    int i = blockIdx.x * blockDim.x + threadIdx.x;   // 0 .. 2097151
    int seg, base;
    if (i < 524288)       { seg = i >> 17;          base = (i & 131071); }       // wq..wo
    else if (i < 1048576) { seg = 4;                base = i - 524288; }         // w1
    else if (i < 1572864) { seg = 5;                base = i - 1048576; }        // w2
    else                  { seg = 6;                base = i - 1572864; }        // wout
    const float* in  = pa.src[seg];
    __half*      out = pa.dst[seg];
    float4 a = reinterpret_cast<const float4*>(in)[2 * base];
    float4 b = reinterpret_cast<const float4*>(in)[2 * base + 1];
    uint4 u;
    u.x = packh2(a.x, a.y); u.y = packh2(a.z, a.w);
    u.z = packh2(b.x, b.y); u.w = packh2(b.z, b.w);
    reinterpret_cast<uint4*>(out)[base] = u;
}

// ---------------------------------------------------------------------------
// LayerNorm: fp32 in, fp16 out
// ---------------------------------------------------------------------------
__global__ void ln_kernel(const float* __restrict__ in,
                          const float* __restrict__ gam,
                          const float* __restrict__ bet,
                          __half* __restrict__ out)
{
    __shared__ float r1[8], r2[8];
    __shared__ float s_mu, s_rstd;
    int row = blockIdx.x, tid = threadIdx.x;

    const float4* p = reinterpret_cast<const float4*>(in) + (size_t)row * (D_ / 4);
    float4 v = p[tid];
    float s  = v.x + v.y + v.z + v.w;
    float s2 = v.x * v.x + v.y * v.y + v.z * v.z + v.w * v.w;
    #pragma unroll
    for (int o = 16; o; o >>= 1) {
        s  += __shfl_xor_sync(0xffffffffu, s,  o);
        s2 += __shfl_xor_sync(0xffffffffu, s2, o);
    }
    if ((tid & 31) == 0) { r1[tid >> 5] = s; r2[tid >> 5] = s2; }
    __syncthreads();
    if (tid == 0) {
        float a = 0.f, b = 0.f;
        #pragma unroll
        for (int i = 0; i < 8; i++) { a += r1[i]; b += r2[i]; }
        float mu  = a / (float)D_;
        float var = b / (float)D_ - mu * mu;
        s_mu = mu;
        s_rstd = rsqrtf(var + 1e-5f);
    }
    __syncthreads();
    float mu = s_mu, rs = s_rstd;
    float4 g4 = reinterpret_cast<const float4*>(gam)[tid];
    float4 b4 = reinterpret_cast<const float4*>(bet)[tid];
    uint2 o;
    o.x = packh2((v.x - mu) * rs * g4.x + b4.x, (v.y - mu) * rs * g4.y + b4.y);
    o.y = packh2((v.z - mu) * rs * g4.z + b4.z, (v.w - mu) * rs * g4.w + b4.w);
    *reinterpret_cast<uint2*>(out + (size_t)row * D_ + tid * 4) = o;
}

// ---------------------------------------------------------------------------
// FP16 GEMM: C[M,N] = A[M,K] @ W[K,N] (+R). 128x128 tile, BK=32, 3-stage
// cp.async, 8 warps (4m x 2n), warp tile 32x64, mma.m16n8k16.
// A smem [m][k] stride 40 halfs, frags via ldmatrix.x4.
// B smem [k][n] stride 136 halfs, frags via ldmatrix.x4.trans.
// ---------------------------------------------------------------------------
#define ASTH_ 40                         // halfs per A row
#define BSTH_ 136                        // halfs per B row
#define ATILEH_ (128 * ASTH_)            // 5120 halfs / stage
#define BTILEH_ (32 * BSTH_)             // 4352 halfs / stage
#define GEMM_SMEM (3 * (ATILEH_ + BTILEH_) * 2)   // 56832 bytes

template <bool RES, bool OUT16, int NGEM>
__global__ void __launch_bounds__(256, 2)
tgemm_kernel(const __half* __restrict__ A,
             const __half* __restrict__ W0, const __half* __restrict__ W1,
             const __half* __restrict__ W2,
             const float* __restrict__ R,
             void* __restrict__ C0, void* __restrict__ C1, void* __restrict__ C2,
             int M, int N, int K)
{
    extern __shared__ char smraw[];
    __half* Ah = reinterpret_cast<__half*>(smraw);
    __half* Bh = reinterpret_cast<__half*>(smraw + 3 * ATILEH_ * 2);

    const __half* W = W0;
    void* C = C0;
    if (NGEM >= 2) {
        int z = blockIdx.z;
        W = (z == 0) ? W0 : (z == 1) ? W1 : W2;
        C = (z == 0) ? C0 : (z == 1) ? C1 : C2;
    }

    const int tid  = threadIdx.x;
    const int lane = tid & 31;
    const int warp = tid >> 5;
    const int wm   = (warp >> 1) * 32;
    const int wn   = (warp & 1) * 64;
    const int qk   = lane & 3;
    const int qm   = lane >> 2;

    const int bm = blockIdx.y * 128, bn = blockIdx.x * 128;

    // ldmatrix lane-address components
    const int lm_lo3  = lane & 7;
    const int lm_hi8  = (lane >> 3) & 1;
    const int lm_colh = lane >> 4;

    // staging: A rows 0..127 x 2 chunks of 16 halfs; B rows 0..31 x 16 chunks of 8 halfs
    const int arow = tid >> 1;
    const int ach0 = (tid & 1) * 2;
    const int brow = tid >> 3;
    const int bch0 = (tid & 7) * 2;

    const __half* Abase = A + (size_t)bm * K;
    const __half* Wbase = W + bn;

    float acc[2][8][4];
    #pragma unroll
    for (int i = 0; i < 2; i++)
        #pragma unroll
        for (int j = 0; j < 8; j++)
            #pragma unroll
            for (int r = 0; r < 4; r++) acc[i][j][r] = 0.f;

    auto issue_tile = [&](int kt, int st) {
        unsigned abase = (unsigned)__cvta_generic_to_shared(&Ah[st * ATILEH_]);
        unsigned bbase = (unsigned)__cvta_generic_to_shared(&Bh[st * BTILEH_]);
        const __half* Ag = Abase + (size_t)arow * K + kt * 32;
        #pragma unroll
        for (int i = 0; i < 2; i++) {
            int ch = ach0 + i;
            cp16(abase + (unsigned)(arow * ASTH_ + ch * 8) * 2, Ag + ch * 8);
        }
        const __half* Bg = Wbase + (size_t)(kt * 32 + brow) * N;
        #pragma unroll
        for (int i = 0; i < 2; i++) {
            int ch = bch0 + i;
            cp16(bbase + (unsigned)(brow * BSTH_ + ch * 8) * 2, Bg + ch * 8);
        }
        CP_COMMIT();
    };

    const int ntiles = K / 32;

    issue_tile(0, 0);
    issue_tile(1, 1);
    cp_wait<1>();
    __syncthreads();

    for (int it = 0; it < ntiles; it++) {
        const int s = it % 3;
        if (it + 2 < ntiles) issue_tile(it + 2, (it + 2) % 3);

        unsigned asb = (unsigned)__cvta_generic_to_shared(&Ah[s * ATILEH_]);
        unsigned bsb = (unsigned)__cvta_generic_to_shared(&Bh[s * BTILEH_]);

        #pragma unroll
        for (int ks = 0; ks < 2; ks++) {
            const int kk = ks * 16;
            unsigned af[2][4];
            #pragma unroll
            for (int mf = 0; mf < 2; mf++) {
                int m = wm + mf * 16 + lm_hi8 * 8 + lm_lo3;
                unsigned addr = asb + (unsigned)(m * ASTH_ + kk + lm_colh * 8) * 2;
                ldm_x4(af[mf][0], af[mf][1], af[mf][2], af[mf][3], addr);
            }
            #pragma unroll
            for (int nb = 0; nb < 4; nb++) {           // n16 blocks over 64
                int vrow = kk + lm_hi8 * 8 + lm_lo3;
                int vcol = wn + nb * 16 + lm_colh * 8;
                unsigned addr = bsb + (unsigned)(vrow * BSTH_ + vcol) * 2;
                unsigned b0, b1, b2, b3;
                ldm_x4_trans(b0, b1, b2, b3, addr);
                #pragma unroll
                for (int mf = 0; mf < 2; mf++) {
                    mma_f16(acc[mf][2 * nb],     af[mf][0], af[mf][1], af[mf][2], af[mf][3], b0, b1);
                    mma_f16(acc[mf][2 * nb + 1], af[mf][0], af[mf][1], af[mf][2], af[mf][3], b2, b3);
                }
            }
        }

        if (it + 2 < ntiles)       cp_wait<1>();
        else if (it + 1 < ntiles)  cp_wait<0>();
        __syncthreads();
    }

    #pragma unroll
    for (int mf = 0; mf < 2; mf++) {
        int row0 = bm + wm + mf * 16 + qm;
        #pragma unroll
        for (int nf = 0; nf < 8; nf++) {
            int col = bn + wn + nf * 8 + 2 * qk;
            size_t off0 = (size_t)row0 * N + col;
            size_t off1 = (size_t)(row0 + 8) * N + col;
            float c0 = acc[mf][nf][0], c1 = acc[mf][nf][1];
            float c2 = acc[mf][nf][2], c3 = acc[mf][nf][3];
            if (RES) {
                float2 r0 = *reinterpret_cast<const float2*>(R + off0);
                float2 r1 = *reinterpret_cast<const float2*>(R + off1);
                c0 += r0.x; c1 += r0.y;
                c2 += r1.x; c3 += r1.y;
            }
            if (OUT16) {
                __half* Ch = reinterpret_cast<__half*>(C);
                *reinterpret_cast<unsigned*>(Ch + off0) = packh2(c0, c1);
                *reinterpret_cast<unsigned*>(Ch + off1) = packh2(c2, c3);
            } else {
                float* Cf = reinterpret_cast<float*>(C);
                *reinterpret_cast<float2*>(Cf + off0) = make_float2(c0, c1);
                *reinterpret_cast<float2*>(Cf + off1) = make_float2(c2, c3);
            }
        }
    }
}

// ---------------------------------------------------------------------------
// Fused FFN (fp16): C = fp16(silu(A@W1) * (A@W2)). 128m x 64n per matrix,
// 8 warps (4m x 2n), warp tile 32x32 per matrix, dual accumulators.
// B smem = [k][ W1 cols 0..63 | W2 cols 64..127 ] stride 136 halfs.
// ---------------------------------------------------------------------------
__global__ void __launch_bounds__(256, 2)
ffn_kernel(const __half* __restrict__ A,
           const __half* __restrict__ W1h, const __half* __restrict__ W2h,
           __half* __restrict__ C, int M, int N, int K)
{
    extern __shared__ char smraw[];
    __half* Ah = reinterpret_cast<__half*>(smraw);
    __half* Bh = reinterpret_cast<__half*>(smraw + 3 * ATILEH_ * 2);

    const int tid  = threadIdx.x;
    const int lane = tid & 31;
    const int warp = tid >> 5;
    const int wm   = (warp >> 1) * 32;
    const int wn   = (warp & 1) * 32;
    const int qk   = lane & 3;
    const int qm   = lane >> 2;

    const int bm = blockIdx.y * 128, bn = blockIdx.x * 64;

    const int lm_lo3  = lane & 7;
    const int lm_hi8  = (lane >> 3) & 1;
    const int lm_colh = lane >> 4;

    const int arow = tid >> 1;
    const int ach0 = (tid & 1) * 2;
    const int brow = tid >> 3;
    const int bch0 = (tid & 7) * 2;

    const __half* Abase = A + (size_t)bm * K;

    float acc1[2][4][4], acc2[2][4][4];
    #pragma unroll
    for (int i = 0; i < 2; i++)
        #pragma unroll
        for (int j = 0; j < 4; j++)
            #pragma unroll
            for (int r = 0; r < 4; r++) { acc1[i][j][r] = 0.f; acc2[i][j][r] = 0.f; }

    auto issue_tile = [&](int kt, int st) {
        unsigned abase = (unsigned)__cvta_generic_to_shared(&Ah[st * ATILEH_]);
        unsigned bbase = (unsigned)__cvta_generic_to_shared(&Bh[st * BTILEH_]);
        const __half* Ag = Abase + (size_t)arow * K + kt * 32;
        #pragma unroll
        for (int i = 0; i < 2; i++) {
            int ch = ach0 + i;
            cp16(abase + (unsigned)(arow * ASTH_ + ch * 8) * 2, Ag + ch * 8);
        }
        #pragma unroll
        for (int i = 0; i < 2; i++) {
            int ch = bch0 + i;                  // 0..15; cols ch*8..ch*8+7
            int colc = ch * 8;
            const __half* Bg = (colc < 64)
                ? (W1h + (size_t)(kt * 32 + brow) * N + bn + colc)
                : (W2h + (size_t)(kt * 32 + brow) * N + bn + colc - 64);
            cp16(bbase + (unsigned)(brow * BSTH_ + colc) * 2, Bg);
        }
        CP_COMMIT();
    };

    const int ntiles = K / 32;

    issue_tile(0, 0);
    issue_tile(1, 1);
    cp_wait<1>();
    __syncthreads();

    for (int it = 0; it < ntiles; it++) {
        const int s = it % 3;
        if (it + 2 < ntiles) issue_tile(it + 2, (it + 2) % 3);

        unsigned asb = (unsigned)__cvta_generic_to_shared(&Ah[s * ATILEH_]);
        unsigned bsb = (unsigned)__cvta_generic_to_shared(&Bh[s * BTILEH_]);

        #pragma unroll
        for (int ks = 0; ks < 2; ks++) {
            const int kk = ks * 16;
            unsigned af[2][4];
            #pragma unroll
            for (int mf = 0; mf < 2; mf++) {
                int m = wm + mf * 16 + lm_hi8 * 8 + lm_lo3;
                unsigned addr = asb + (unsigned)(m * ASTH_ + kk + lm_colh * 8) * 2;
                ldm_x4(af[mf][0], af[mf][1], af[mf][2], af[mf][3], addr);
            }
            #pragma unroll
            for (int nb = 0; nb < 2; nb++) {          // n16 blocks over 32
                int vrow = kk + lm_hi8 * 8 + lm_lo3;
                int vcol1 = wn + nb * 16 + lm_colh * 8;
                unsigned a1_ = bsb + (unsigned)(vrow * BSTH_ + vcol1) * 2;
                unsigned a2_ = bsb + (unsigned)(vrow * BSTH_ + vcol1 + 64) * 2;
                unsigned b10, b11, b12, b13, b20, b21, b22, b23;
                ldm_x4_trans(b10, b11, b12, b13, a1_);
                ldm_x4_trans(b20, b21, b22, b23, a2_);
                #pragma unroll
                for (int mf = 0; mf < 2; mf++) {
                    mma_f16(acc1[mf][2 * nb],     af[mf][0], af[mf][1], af[mf][2], af[mf][3], b10, b11);
                    mma_f16(acc1[mf][2 * nb + 1], af[mf][0], af[mf][1], af[mf][2], af[mf][3], b12, b13);
                    mma_f16(acc2[mf][2 * nb],     af[mf][0], af[mf][1], af[mf][2], af[mf][3], b20, b21);
                    mma_f16(acc2[mf][2 * nb + 1], af[mf][0], af[mf][1], af[mf][2], af[mf][3], b22, b23);
                }
            }
        }

        if (it + 2 < ntiles)       cp_wait<1>();
        else if (it + 1 < ntiles)  cp_wait<0>();
        __syncthreads();
    }

    #pragma unroll
    for (int mf = 0; mf < 2; mf++) {
        int row0 = bm + wm + mf * 16 + qm;
        #pragma unroll
        for (int nf = 0; nf < 4; nf++) {
            int col = bn + wn + nf * 8 + 2 * qk;
            size_t off0 = (size_t)row0 * N + col;
            size_t off1 = (size_t)(row0 + 8) * N + col;
            float a0 = acc1[mf][nf][0], a1 = acc1[mf][nf][1];
            float a2 = acc1[mf][nf][2], a3 = acc1[mf][nf][3];
            float g0 = acc2[mf][nf][0], g1 = acc2[mf][nf][1];
            float g2 = acc2[mf][nf][2], g3 = acc2[mf][nf][3];
            *reinterpret_cast<unsigned*>(C + off0) =
                packh2(a0 / (1.f + __expf(-a0)) * g0, a1 / (1.f + __expf(-a1)) * g1);
            *reinterpret_cast<unsigned*>(C + off1) =
                packh2(a2 / (1.f + __expf(-a2)) * g2, a3 / (1.f + __expf(-a3)) * g3);
        }
    }
}

// ---------------------------------------------------------------------------
// Flash attention fp16 (V via ldmatrix.trans) — round-12 configuration
// ---------------------------------------------------------------------------
#define STH_ 72
#define ATTN_SMEM ((64 * STH_ * 6) * 2 + 256 * 4)

__global__ void __launch_bounds__(256)
attn_kernel(const __half* __restrict__ Q, const __half* __restrict__ K,
            const __half* __restrict__ V, __half* __restrict__ O)
{
    extern __shared__ char smraw[];
    __half* Qs = reinterpret_cast<__half*>(smraw);
    __half* Ks = Qs + 64 * STH_;
    __half* Vs = Ks + 2 * 64 * STH_;
    __half* Ps = Vs + 2 * 64 * STH_;
    float* redmx = reinterpret_cast<float*>(Ps + 64 * STH_);
    float* redsm = redmx + 128;

    const int tid  = threadIdx.x;
    const int lane = tid & 31;
    const int warp = tid >> 5;
    const int wm   = (warp >> 1) * 16;
    const int wnh  = warp & 1;
    const int qm   = lane >> 2;
    const int qk   = lane & 3;

    const int b = blockIdx.y >> 4, h = blockIdx.y & 15;
    const int qi = gridDim.x - 1 - blockIdx.x;
    const int qb = qi * 64;

    const __half* Qb = Q + (size_t)b * T_ * D_ + h * HD_;
    const __half* Kb = K + (size_t)b * T_ * D_ + h * HD_;
    const __half* Vb = V + (size_t)b * T_ * D_ + h * HD_;

    const int lrow = tid >> 2, lch0 = (tid & 3) * 2;

    auto issue_kv = [&](int j, int s) {
        unsigned kb_ = (unsigned)__cvta_generic_to_shared(&Ks[s * 64 * STH_]);
        unsigned vb_ = (unsigned)__cvta_generic_to_shared(&Vs[s * 64 * STH_]);
        const __half* Kg = Kb + (size_t)(j * 64 + lrow) * D_;
        const __half* Vg = Vb + (size_t)(j * 64 + lrow) * D_;
        #pragma unroll
        for (int i = 0; i < 2; i++) {
            int ch = lch0 + i;
            cp16(kb_ + (unsigned)(lrow * STH_ + ch * 8) * 2, Kg + ch * 8);
            cp16(vb_ + (unsigned)(lrow * STH_ + ch * 8) * 2, Vg + ch * 8);
        }
        CP_COMMIT();
    };

    {
        unsigned qs_ = (unsigned)__cvta_generic_to_shared(Qs);
        const __half* Qg = Qb + (size_t)(qb + lrow) * D_;
        #pragma unroll
        for (int i = 0; i < 2; i++) {
            int ch = lch0 + i;
            cp16(qs_ + (unsigned)(lrow * STH_ + ch * 8) * 2, Qg + ch * 8);
        }
        CP_COMMIT();
    }
    issue_kv(0, 0);
    cp_wait<0>();
    __syncthreads();

    float acc[4][4];
    float m_i[2], l_i[2];
    m_i[0] = m_i[1] = -1e30f;
    l_i[0] = l_i[1] = 0.f;
    #pragma unroll
    for (int nf = 0; nf < 4; nf++)
        #pragma unroll
        for (int c = 0; c < 4; c++) acc[nf][c] = 0.f;

    const int r0l = wm + qm;
    const int ntile = qi + 1;

    const int lm_lo3  = lane & 7;
    const int lm_hi8  = (lane >> 3) & 1;
    const int lm_colh = lane >> 4;

    for (int j = 0; j < ntile; j++) {
        const int s = j & 1;
        if (j + 1 < ntile) issue_kv(j + 1, s ^ 1);

        const __half* Ksb = &Ks[s * 64 * STH_];
        const __half* Vsb = &Vs[s * 64 * STH_];
        unsigned vbase = (unsigned)__cvta_generic_to_shared(Vsb);

        float sv4[4][4];
        #pragma unroll
        for (int nf = 0; nf < 4; nf++)
            #pragma unroll
            for (int c = 0; c < 4; c++) sv4[nf][c] = 0.f;

        #pragma unroll
        for (int ks = 0; ks < 4; ks++) {
            const int kk = ks * 16;
            unsigned a0 = *reinterpret_cast<const unsigned*>(&Qs[(size_t)r0l * STH_ + kk + 2 * qk]);
            unsigned a1 = *reinterpret_cast<const unsigned*>(&Qs[(size_t)(r0l + 8) * STH_ + kk + 2 * qk]);
            unsigned a2 = *reinterpret_cast<const unsigned*>(&Qs[(size_t)r0l * STH_ + kk + 2 * qk + 8]);
            unsigned a3 = *reinterpret_cast<const unsigned*>(&Qs[(size_t)(r0l + 8) * STH_ + kk + 2 * qk + 8]);
            #pragma unroll
            for (int nf = 0; nf < 4; nf++) {
                int n = wnh * 32 + nf * 8 + qm;
                unsigned b0 = *reinterpret_cast<const unsigned*>(&Ksb[(size_t)n * STH_ + kk + 2 * qk]);
                unsigned b1 = *reinterpret_cast<const unsigned*>(&Ksb[(size_t)n * STH_ + kk + 2 * qk + 8]);
                mma_f16(sv4[nf], a0, a1, a2, a3, b0, b1);
            }
        }

        const bool diag = ((j * 64) == qb);
        #pragma unroll
        for (int nf = 0; nf < 4; nf++) {
            int colb = wnh * 32 + nf * 8 + 2 * qk;
            #pragma unroll
            for (int c = 0; c < 4; c++) {
                int col = colb + (c & 1);
                int row = r0l + ((c >> 1) ? 8 : 0);
                float sv = sv4[nf][c] * 0.125f;
                if (diag && (col > row)) sv = -1e30f;
                sv4[nf][c] = sv;
            }
        }

        float mx0 = -1e30f, mx1 = -1e30f;
        #pragma unroll
        for (int nf = 0; nf < 4; nf++) {
            mx0 = fmaxf(mx0, fmaxf(sv4[nf][0], sv4[nf][1]));
            mx1 = fmaxf(mx1, fmaxf(sv4[nf][2], sv4[nf][3]));
        }
        #pragma unroll
        for (int o = 1; o < 4; o <<= 1) {
            mx0 = fmaxf(mx0, __shfl_xor_sync(0xffffffffu, mx0, o));
            mx1 = fmaxf(mx1, __shfl_xor_sync(0xffffffffu, mx1, o));
        }
        if ((lane & 3) == 0) {
            redmx[wnh * 64 + r0l]     = mx0;
            redmx[wnh * 64 + r0l + 8] = mx1;
        }
        __syncthreads();
        float mn0 = fmaxf(m_i[0], fmaxf(redmx[r0l],     redmx[64 + r0l]));
        float mn1 = fmaxf(m_i[1], fmaxf(redmx[r0l + 8], redmx[64 + r0l + 8]));

        float sum0 = 0.f, sum1 = 0.f;
        #pragma unroll
        for (int nf = 0; nf < 4; nf++) {
            int colb = wnh * 32 + nf * 8 + 2 * qk;
            float p0 = __expf(sv4[nf][0] - mn0);
            float p1 = __expf(sv4[nf][1] - mn0);
            float p2 = __expf(sv4[nf][2] - mn1);
            float p3 = __expf(sv4[nf][3] - mn1);
            sum0 += p0 + p1;
            sum1 += p2 + p3;
            *reinterpret_cast<unsigned*>(&Ps[(size_t)r0l * STH_ + colb])       = packh2(p0, p1);
            *reinterpret_cast<unsigned*>(&Ps[(size_t)(r0l + 8) * STH_ + colb]) = packh2(p2, p3);
        }
        #pragma unroll
        for (int o = 1; o < 4; o <<= 1) {
            sum0 += __shfl_xor_sync(0xffffffffu, sum0, o);
            sum1 += __shfl_xor_sync(0xffffffffu, sum1, o);
        }
        if ((lane & 3) == 0) {
            redsm[wnh * 64 + r0l]     = sum0;
            redsm[wnh * 64 + r0l + 8] = sum1;
        }
        __syncthreads();
        float ts0 = redsm[r0l]     + redsm[64 + r0l];
        float ts1 = redsm[r0l + 8] + redsm[64 + r0l + 8];

        float al0 = __expf(m_i[0] - mn0);
        float al1 = __expf(m_i[1] - mn1);
        l_i[0] = l_i[0] * al0 + ts0;  m_i[0] = mn0;
        l_i[1] = l_i[1] * al1 + ts1;  m_i[1] = mn1;
        #pragma unroll
        for (int nf = 0; nf < 4; nf++) {
            acc[nf][0] *= al0; acc[nf][1] *= al0;
            acc[nf][2] *= al1; acc[nf][3] *= al1;
        }

        #pragma unroll
        for (int ks = 0; ks < 4; ks++) {
            const int kk = ks * 16;
            unsigned a0 = *reinterpret_cast<const unsigned*>(&Ps[(size_t)r0l * STH_ + kk + 2 * qk]);
            unsigned a1 = *reinterpret_cast<const unsigned*>(&Ps[(size_t)(r0l + 8) * STH_ + kk + 2 * qk]);
            unsigned a2 = *reinterpret_cast<const unsigned*>(&Ps[(size_t)r0l * STH_ + kk + 2 * qk + 8]);
            unsigned a3 = *reinterpret_cast<const unsigned*>(&Ps[(size_t)(r0l + 8) * STH_ + kk + 2 * qk + 8]);
            #pragma unroll
            for (int np = 0; np < 2; np++) {
                int n0 = wnh * 32 + np * 16;
                int vrow = kk + lm_hi8 * 8 + lm_lo3;
                int vcol = n0 + lm_colh * 8;
                unsigned addr = vbase + (unsigned)(vrow * STH_ + vcol) * 2;
                unsigned r0, r1, r2, r3;
                ldm_x4_trans(r0, r1, r2, r3, addr);
                mma_f16(acc[2 * np],     a0, a1, a2, a3, r0, r1);
                mma_f16(acc[2 * np + 1], a0, a1, a2, a3, r2, r3);
            }
        }

        if (j + 1 < ntile) cp_wait<0>();
        __syncthreads();
    }

    {
        float inv0 = 1.0f / l_i[0], inv1 = 1.0f / l_i[1];
        #pragma unroll
        for (int nf = 0; nf < 4; nf++) {
            int col = h * HD_ + wnh * 32 + nf * 8 + 2 * qk;
            size_t off0 = (size_t)b * T_ * D_ + (size_t)(qb + r0l) * D_ + col;
            size_t off1 = (size_t)b * T_ * D_ + (size_t)(qb + r0l + 8) * D_ + col;
            *reinterpret_cast<unsigned*>(O + off0) = packh2(acc[nf][0] * inv0, acc[nf][1] * inv0);
            *reinterpret_cast<unsigned*>(O + off1) = packh2(acc[nf][2] * inv1, acc[nf][3] * inv1);
        }
    }
}

// ---------------------------------------------------------------------------
// Orchestration
// ---------------------------------------------------------------------------
extern "C" void kernel_launch(void* const* d_in, const int* in_sizes, int n_in,
                              void* d_out, int out_size)
{
    const float* h    = (const float*)d_in[0];
    const float* alng = (const float*)d_in[2];
    const float* alnb = (const float*)d_in[3];
    const float* mlng = (const float*)d_in[4];
    const float* mlnb = (const float*)d_in[5];
    const float* wq   = (const float*)d_in[6];
    const float* wk   = (const float*)d_in[7];
    const float* wv   = (const float*)d_in[8];
    const float* wo   = (const float*)d_in[9];
    const float* w1   = (const float*)d_in[10];
    const float* w2   = (const float*)d_in[11];
    const float* wout = (const float*)d_in[12];
    float* out = (float*)d_out;

    __half *px, *pq, *pk, *pv, *po, *py, *pa;
    float *ph2;
    __half *pwq, *pwk, *pwv, *pwo, *pw1, *pw2, *pwout;
    cudaGetSymbolAddress((void**)&px,  g_x);
    cudaGetSymbolAddress((void**)&pq,  g_q);
    cudaGetSymbolAddress((void**)&pk,  g_k);
    cudaGetSymbolAddress((void**)&pv,  g_v);
    cudaGetSymbolAddress((void**)&po,  g_o);
    cudaGetSymbolAddress((void**)&ph2, g_h2);
    cudaGetSymbolAddress((void**)&py,  g_y);
    cudaGetSymbolAddress((void**)&pa,  g_a);
    cudaGetSymbolAddress((void**)&pwq,   g_wq);
    cudaGetSymbolAddress((void**)&pwk,   g_wk);
    cudaGetSymbolAddress((void**)&pwv,   g_wv);
    cudaGetSymbolAddress((void**)&pwo,   g_wo);
    cudaGetSymbolAddress((void**)&pw1,   g_w1);
    cudaGetSymbolAddress((void**)&pw2,   g_w2);
    cudaGetSymbolAddress((void**)&pwout, g_wout);

    cudaFuncSetAttribute(attn_kernel, cudaFuncAttributeMaxDynamicSharedMemorySize, ATTN_SMEM);
    cudaFuncSetAttribute(ffn_kernel,  cudaFuncAttributeMaxDynamicSharedMemorySize, GEMM_SMEM);
    cudaFuncSetAttribute(tgemm_kernel<false, true, 3>, cudaFuncAttributeMaxDynamicSharedMemorySize, GEMM_SMEM);
    cudaFuncSetAttribute(tgemm_kernel<true, false, 1>, cudaFuncAttributeMaxDynamicSharedMemorySize, GEMM_SMEM);

    // all weights -> fp16 in ONE launch
    PackArgs pargs;
    pargs.src[0] = wq;   pargs.dst[0] = pwq;
    pargs.src[1] = wk;   pargs.dst[1] = pwk;
    pargs.src[2] = wv;   pargs.dst[2] = pwv;
    pargs.src[3] = wo;   pargs.dst[3] = pwo;
    pargs.src[4] = w1;   pargs.dst[4] = pw1;
    pargs.src[5] = w2;   pargs.dst[5] = pw2;
    pargs.src[6] = wout; pargs.dst[6] = pwout;
    packall_kernel<<<2097152 / 256, 256>>>(pargs);

    dim3 gQKV(D_ / 128, ROWS_ / 128, 3);    // (8, 64, 3)
    dim3 gD(D_ / 128, ROWS_ / 128);         // (8, 64)
    dim3 gFFN(FFN_ / 64, ROWS_ / 128);      // (64, 64)

    // x = fp16(LN(h))
    ln_kernel<<<ROWS_, 256>>>(h, alng, alnb, px);
    // q,k,v = fp16(x @ {wq,wk,wv})
    tgemm_kernel<false, true, 3><<<gQKV, 256, GEMM_SMEM>>>(px, pwq, pwk, pwv, nullptr,
                                                           pq, pk, pv, ROWS_, D_, D_);
    // o = fp16(attention(q,k,v))
    attn_kernel<<<dim3(T_ / 64, B_ * H_), 256, ATTN_SMEM>>>(pq, pk, pv, po);
    // h2 = h + o @ wo   (fp32)
    tgemm_kernel<true, false, 1><<<gD, 256, GEMM_SMEM>>>(po, pwo, nullptr, nullptr, h,
                                                         ph2, nullptr, nullptr, ROWS_, D_, D_);
    // y = fp16(LN(h2))
    ln_kernel<<<ROWS_, 256>>>(ph2, mlng, mlnb, py);
    // a = fp16(silu(y@w1) * (y@w2))
    ffn_kernel<<<gFFN, 256, GEMM_SMEM>>>(py, pw1, pw2, pa, ROWS_, FFN_, D_);
    // out = h2 + a @ wout   (fp32)
    tgemm_kernel<true, false, 1><<<gD, 256, GEMM_SMEM>>>(pa, pwout, nullptr, nullptr, ph2,
                                                         out, nullptr, nullptr, ROWS_, D_, FFN_);
}

// round 17
// speedup vs baseline: 1.2867x; 1.0264x over previous
#include <cuda_runtime.h>
#include <cuda_fp16.h>
#include <math.h>

// Problem constants
#define B_    4
#define T_    2048
#define D_    1024
#define H_    16
#define HD_   64
#define FFN_  4096
#define ROWS_ (B_ * T_)        // 8192

// ---------------------------------------------------------------------------
// Scratch (device globals)
// ---------------------------------------------------------------------------
__device__ __half g_x [ROWS_ * D_];
__device__ __half g_q [ROWS_ * D_];
__device__ __half g_k [ROWS_ * D_];
__device__ __half g_v [ROWS_ * D_];
__device__ __half g_o [ROWS_ * D_];
__device__ float  g_h2[ROWS_ * D_];
__device__ __half g_y [ROWS_ * D_];
__device__ __half g_a [ROWS_ * FFN_];

// plain fp16 weights [k][n]
__device__ __half g_wq [D_ * D_];
__device__ __half g_wk [D_ * D_];
__device__ __half g_wv [D_ * D_];
__device__ __half g_wo [D_ * D_];
__device__ __half g_w1 [D_ * FFN_];
__device__ __half g_w2 [D_ * FFN_];
__device__ __half g_wout[FFN_ * D_];

// ---------------------------------------------------------------------------
// Helpers
// ---------------------------------------------------------------------------
__device__ __forceinline__ unsigned packh2(float lo, float hi) {
    __half2 h = __floats2half2_rn(lo, hi);
    return *reinterpret_cast<unsigned*>(&h);
}

__device__ __forceinline__ void mma_f16(float c[4],
                                        unsigned a0, unsigned a1, unsigned a2, unsigned a3,
                                        unsigned b0, unsigned b1) {
    asm volatile(
        "mma.sync.aligned.m16n8k16.row.col.f32.f16.f16.f32 "
        "{%0,%1,%2,%3}, {%4,%5,%6,%7}, {%8,%9}, {%0,%1,%2,%3};"
        : "+f"(c[0]), "+f"(c[1]), "+f"(c[2]), "+f"(c[3])
        : "r"(a0), "r"(a1), "r"(a2), "r"(a3), "r"(b0), "r"(b1));
}

__device__ __forceinline__ void ldm_x4(unsigned& r0, unsigned& r1,
                                       unsigned& r2, unsigned& r3, unsigned addr) {
    asm volatile("ldmatrix.sync.aligned.m8n8.x4.shared.b16 {%0,%1,%2,%3}, [%4];"
                 : "=r"(r0), "=r"(r1), "=r"(r2), "=r"(r3) : "r"(addr));
}

__device__ __forceinline__ void ldm_x4_trans(unsigned& r0, unsigned& r1,
                                             unsigned& r2, unsigned& r3, unsigned addr) {
    asm volatile("ldmatrix.sync.aligned.m8n8.x4.trans.shared.b16 {%0,%1,%2,%3}, [%4];"
                 : "=r"(r0), "=r"(r1), "=r"(r2), "=r"(r3) : "r"(addr));
}

__device__ __forceinline__ void cp16(unsigned dst, const void* src) {
    asm volatile("cp.async.cg.shared.global [%0], [%1], 16;" :: "r"(dst), "l"(src));
}
#define CP_COMMIT() asm volatile("cp.async.commit_group;" ::: "memory")
template <int N> __device__ __forceinline__ void cp_wait() {
    asm volatile("cp.async.wait_group %0;" :: "n"(N) : "memory");
}

// ---------------------------------------------------------------------------
// Fused fp32 -> fp16 conversion for ALL weights in one launch.
// ---------------------------------------------------------------------------
struct PackArgs {
    const float* src[7];
    __half*      dst[7];
};

__global__ void packall_kernel(PackArgs pa)
{
    int i = blockIdx.x * blockDim.x + threadIdx.x;   // 0 .. 2097151
    int seg, base;
    if (i < 524288)       { seg = i >> 17;          base = (i & 131071); }
    else if (i < 1048576) { seg = 4;                base = i - 524288; }
    else if (i < 1572864) { seg = 5;                base = i - 1048576; }
    else                  { seg = 6;                base = i - 1572864; }
    const float* in  = pa.src[seg];
    __half*      out = pa.dst[seg];
    float4 a = reinterpret_cast<const float4*>(in)[2 * base];
    float4 b = reinterpret_cast<const float4*>(in)[2 * base + 1];
    uint4 u;
    u.x = packh2(a.x, a.y); u.y = packh2(a.z, a.w);
    u.z = packh2(b.x, b.y); u.w = packh2(b.z, b.w);
    reinterpret_cast<uint4*>(out)[base] = u;
}

// ---------------------------------------------------------------------------
// LayerNorm: fp32 in, fp16 out
// ---------------------------------------------------------------------------
__global__ void ln_kernel(const float* __restrict__ in,
                          const float* __restrict__ gam,
                          const float* __restrict__ bet,
                          __half* __restrict__ out)
{
    __shared__ float r1[8], r2[8];
    __shared__ float s_mu, s_rstd;
    int row = blockIdx.x, tid = threadIdx.x;

    const float4* p = reinterpret_cast<const float4*>(in) + (size_t)row * (D_ / 4);
    float4 v = p[tid];
    float s  = v.x + v.y + v.z + v.w;
    float s2 = v.x * v.x + v.y * v.y + v.z * v.z + v.w * v.w;
    #pragma unroll
    for (int o = 16; o; o >>= 1) {
        s  += __shfl_xor_sync(0xffffffffu, s,  o);
        s2 += __shfl_xor_sync(0xffffffffu, s2, o);
    }
    if ((tid & 31) == 0) { r1[tid >> 5] = s; r2[tid >> 5] = s2; }
    __syncthreads();
    if (tid == 0) {
        float a = 0.f, b = 0.f;
        #pragma unroll
        for (int i = 0; i < 8; i++) { a += r1[i]; b += r2[i]; }
        float mu  = a / (float)D_;
        float var = b / (float)D_ - mu * mu;
        s_mu = mu;
        s_rstd = rsqrtf(var + 1e-5f);
    }
    __syncthreads();
    float mu = s_mu, rs = s_rstd;
    float4 g4 = reinterpret_cast<const float4*>(gam)[tid];
    float4 b4 = reinterpret_cast<const float4*>(bet)[tid];
    uint2 o;
    o.x = packh2((v.x - mu) * rs * g4.x + b4.x, (v.y - mu) * rs * g4.y + b4.y);
    o.y = packh2((v.z - mu) * rs * g4.z + b4.z, (v.w - mu) * rs * g4.w + b4.w);
    *reinterpret_cast<uint2*>(out + (size_t)row * D_ + tid * 4) = o;
}

// ---------------------------------------------------------------------------
// FP16 GEMM: C[M,N] = A[M,K] @ W[K,N] (+R). 128x128 tile, BK=32, 3-stage
// cp.async, 8 warps (4m x 2n), warp tile 32x64, mma.m16n8k16.
// ---------------------------------------------------------------------------
#define ASTH_ 40
#define BSTH_ 136
#define ATILEH_ (128 * ASTH_)
#define BTILEH_ (32 * BSTH_)
#define GEMM_SMEM (3 * (ATILEH_ + BTILEH_) * 2)   // 56832 bytes

template <bool RES, bool OUT16, int NGEM>
__global__ void __launch_bounds__(256, 2)
tgemm_kernel(const __half* __restrict__ A,
             const __half* __restrict__ W0, const __half* __restrict__ W1,
             const __half* __restrict__ W2,
             const float* __restrict__ R,
             void* __restrict__ C0, void* __restrict__ C1, void* __restrict__ C2,
             int M, int N, int K)
{
    extern __shared__ char smraw[];
    __half* Ah = reinterpret_cast<__half*>(smraw);
    __half* Bh = reinterpret_cast<__half*>(smraw + 3 * ATILEH_ * 2);

    const __half* W = W0;
    void* C = C0;
    if (NGEM >= 2) {
        int z = blockIdx.z;
        W = (z == 0) ? W0 : (z == 1) ? W1 : W2;
        C = (z == 0) ? C0 : (z == 1) ? C1 : C2;
    }

    const int tid  = threadIdx.x;
    const int lane = tid & 31;
    const int warp = tid >> 5;
    const int wm   = (warp >> 1) * 32;
    const int wn   = (warp & 1) * 64;
    const int qk   = lane & 3;
    const int qm   = lane >> 2;

    const int bm = blockIdx.y * 128, bn = blockIdx.x * 128;

    const int lm_lo3  = lane & 7;
    const int lm_hi8  = (lane >> 3) & 1;
    const int lm_colh = lane >> 4;

    const int arow = tid >> 1;
    const int ach0 = (tid & 1) * 2;
    const int brow = tid >> 3;
    const int bch0 = (tid & 7) * 2;

    const __half* Abase = A + (size_t)bm * K;
    const __half* Wbase = W + bn;

    float acc[2][8][4];
    #pragma unroll
    for (int i = 0; i < 2; i++)
        #pragma unroll
        for (int j = 0; j < 8; j++)
            #pragma unroll
            for (int r = 0; r < 4; r++) acc[i][j][r] = 0.f;

    auto issue_tile = [&](int kt, int st) {
        unsigned abase = (unsigned)__cvta_generic_to_shared(&Ah[st * ATILEH_]);
        unsigned bbase = (unsigned)__cvta_generic_to_shared(&Bh[st * BTILEH_]);
        const __half* Ag = Abase + (size_t)arow * K + kt * 32;
        #pragma unroll
        for (int i = 0; i < 2; i++) {
            int ch = ach0 + i;
            cp16(abase + (unsigned)(arow * ASTH_ + ch * 8) * 2, Ag + ch * 8);
        }
        const __half* Bg = Wbase + (size_t)(kt * 32 + brow) * N;
        #pragma unroll
        for (int i = 0; i < 2; i++) {
            int ch = bch0 + i;
            cp16(bbase + (unsigned)(brow * BSTH_ + ch * 8) * 2, Bg + ch * 8);
        }
        CP_COMMIT();
    };

    const int ntiles = K / 32;

    issue_tile(0, 0);
    issue_tile(1, 1);
    cp_wait<1>();
    __syncthreads();

    for (int it = 0; it < ntiles; it++) {
        const int s = it % 3;
        if (it + 2 < ntiles) issue_tile(it + 2, (it + 2) % 3);

        unsigned asb = (unsigned)__cvta_generic_to_shared(&Ah[s * ATILEH_]);
        unsigned bsb = (unsigned)__cvta_generic_to_shared(&Bh[s * BTILEH_]);

        #pragma unroll
        for (int ks = 0; ks < 2; ks++) {
            const int kk = ks * 16;
            unsigned af[2][4];
            #pragma unroll
            for (int mf = 0; mf < 2; mf++) {
                int m = wm + mf * 16 + lm_hi8 * 8 + lm_lo3;
                unsigned addr = asb + (unsigned)(m * ASTH_ + kk + lm_colh * 8) * 2;
                ldm_x4(af[mf][0], af[mf][1], af[mf][2], af[mf][3], addr);
            }
            #pragma unroll
            for (int nb = 0; nb < 4; nb++) {
                int vrow = kk + lm_hi8 * 8 + lm_lo3;
                int vcol = wn + nb * 16 + lm_colh * 8;
                unsigned addr = bsb + (unsigned)(vrow * BSTH_ + vcol) * 2;
                unsigned b0, b1, b2, b3;
                ldm_x4_trans(b0, b1, b2, b3, addr);
                #pragma unroll
                for (int mf = 0; mf < 2; mf++) {
                    mma_f16(acc[mf][2 * nb],     af[mf][0], af[mf][1], af[mf][2], af[mf][3], b0, b1);
                    mma_f16(acc[mf][2 * nb + 1], af[mf][0], af[mf][1], af[mf][2], af[mf][3], b2, b3);
                }
            }
        }

        if (it + 2 < ntiles)       cp_wait<1>();
        else if (it + 1 < ntiles)  cp_wait<0>();
        __syncthreads();
    }

    #pragma unroll
    for (int mf = 0; mf < 2; mf++) {
        int row0 = bm + wm + mf * 16 + qm;
        #pragma unroll
        for (int nf = 0; nf < 8; nf++) {
            int col = bn + wn + nf * 8 + 2 * qk;
            size_t off0 = (size_t)row0 * N + col;
            size_t off1 = (size_t)(row0 + 8) * N + col;
            float c0 = acc[mf][nf][0], c1 = acc[mf][nf][1];
            float c2 = acc[mf][nf][2], c3 = acc[mf][nf][3];
            if (RES) {
                float2 r0 = *reinterpret_cast<const float2*>(R + off0);
                float2 r1 = *reinterpret_cast<const float2*>(R + off1);
                c0 += r0.x; c1 += r0.y;
                c2 += r1.x; c3 += r1.y;
            }
            if (OUT16) {
                __half* Ch = reinterpret_cast<__half*>(C);
                *reinterpret_cast<unsigned*>(Ch + off0) = packh2(c0, c1);
                *reinterpret_cast<unsigned*>(Ch + off1) = packh2(c2, c3);
            } else {
                float* Cf = reinterpret_cast<float*>(C);
                *reinterpret_cast<float2*>(Cf + off0) = make_float2(c0, c1);
                *reinterpret_cast<float2*>(Cf + off1) = make_float2(c2, c3);
            }
        }
    }
}

// ---------------------------------------------------------------------------
// Fused FFN (fp16): C = fp16(silu(A@W1) * (A@W2)). 128m x 64n per matrix.
// ---------------------------------------------------------------------------
__global__ void __launch_bounds__(256, 2)
ffn_kernel(const __half* __restrict__ A,
           const __half* __restrict__ W1h, const __half* __restrict__ W2h,
           __half* __restrict__ C, int M, int N, int K)
{
    extern __shared__ char smraw[];
    __half* Ah = reinterpret_cast<__half*>(smraw);
    __half* Bh = reinterpret_cast<__half*>(smraw + 3 * ATILEH_ * 2);

    const int tid  = threadIdx.x;
    const int lane = tid & 31;
    const int warp = tid >> 5;
    const int wm   = (warp >> 1) * 32;
    const int wn   = (warp & 1) * 32;
    const int qk   = lane & 3;
    const int qm   = lane >> 2;

    const int bm = blockIdx.y * 128, bn = blockIdx.x * 64;

    const int lm_lo3  = lane & 7;
    const int lm_hi8  = (lane >> 3) & 1;
    const int lm_colh = lane >> 4;

    const int arow = tid >> 1;
    const int ach0 = (tid & 1) * 2;
    const int brow = tid >> 3;
    const int bch0 = (tid & 7) * 2;

    const __half* Abase = A + (size_t)bm * K;

    float acc1[2][4][4], acc2[2][4][4];
    #pragma unroll
    for (int i = 0; i < 2; i++)
        #pragma unroll
        for (int j = 0; j < 4; j++)
            #pragma unroll
            for (int r = 0; r < 4; r++) { acc1[i][j][r] = 0.f; acc2[i][j][r] = 0.f; }

    auto issue_tile = [&](int kt, int st) {
        unsigned abase = (unsigned)__cvta_generic_to_shared(&Ah[st * ATILEH_]);
        unsigned bbase = (unsigned)__cvta_generic_to_shared(&Bh[st * BTILEH_]);
        const __half* Ag = Abase + (size_t)arow * K + kt * 32;
        #pragma unroll
        for (int i = 0; i < 2; i++) {
            int ch = ach0 + i;
            cp16(abase + (unsigned)(arow * ASTH_ + ch * 8) * 2, Ag + ch * 8);
        }
        #pragma unroll
        for (int i = 0; i < 2; i++) {
            int ch = bch0 + i;
            int colc = ch * 8;
            const __half* Bg = (colc < 64)
                ? (W1h + (size_t)(kt * 32 + brow) * N + bn + colc)
                : (W2h + (size_t)(kt * 32 + brow) * N + bn + colc - 64);
            cp16(bbase + (unsigned)(brow * BSTH_ + colc) * 2, Bg);
        }
        CP_COMMIT();
    };

    const int ntiles = K / 32;

    issue_tile(0, 0);
    issue_tile(1, 1);
    cp_wait<1>();
    __syncthreads();

    for (int it = 0; it < ntiles; it++) {
        const int s = it % 3;
        if (it + 2 < ntiles) issue_tile(it + 2, (it + 2) % 3);

        unsigned asb = (unsigned)__cvta_generic_to_shared(&Ah[s * ATILEH_]);
        unsigned bsb = (unsigned)__cvta_generic_to_shared(&Bh[s * BTILEH_]);

        #pragma unroll
        for (int ks = 0; ks < 2; ks++) {
            const int kk = ks * 16;
            unsigned af[2][4];
            #pragma unroll
            for (int mf = 0; mf < 2; mf++) {
                int m = wm + mf * 16 + lm_hi8 * 8 + lm_lo3;
                unsigned addr = asb + (unsigned)(m * ASTH_ + kk + lm_colh * 8) * 2;
                ldm_x4(af[mf][0], af[mf][1], af[mf][2], af[mf][3], addr);
            }
            #pragma unroll
            for (int nb = 0; nb < 2; nb++) {
                int vrow = kk + lm_hi8 * 8 + lm_lo3;
                int vcol1 = wn + nb * 16 + lm_colh * 8;
                unsigned a1_ = bsb + (unsigned)(vrow * BSTH_ + vcol1) * 2;
                unsigned a2_ = bsb + (unsigned)(vrow * BSTH_ + vcol1 + 64) * 2;
                unsigned b10, b11, b12, b13, b20, b21, b22, b23;
                ldm_x4_trans(b10, b11, b12, b13, a1_);
                ldm_x4_trans(b20, b21, b22, b23, a2_);
                #pragma unroll
                for (int mf = 0; mf < 2; mf++) {
                    mma_f16(acc1[mf][2 * nb],     af[mf][0], af[mf][1], af[mf][2], af[mf][3], b10, b11);
                    mma_f16(acc1[mf][2 * nb + 1], af[mf][0], af[mf][1], af[mf][2], af[mf][3], b12, b13);
                    mma_f16(acc2[mf][2 * nb],     af[mf][0], af[mf][1], af[mf][2], af[mf][3], b20, b21);
                    mma_f16(acc2[mf][2 * nb + 1], af[mf][0], af[mf][1], af[mf][2], af[mf][3], b22, b23);
                }
            }
        }

        if (it + 2 < ntiles)       cp_wait<1>();
        else if (it + 1 < ntiles)  cp_wait<0>();
        __syncthreads();
    }

    #pragma unroll
    for (int mf = 0; mf < 2; mf++) {
        int row0 = bm + wm + mf * 16 + qm;
        #pragma unroll
        for (int nf = 0; nf < 4; nf++) {
            int col = bn + wn + nf * 8 + 2 * qk;
            size_t off0 = (size_t)row0 * N + col;
            size_t off1 = (size_t)(row0 + 8) * N + col;
            float a0 = acc1[mf][nf][0], a1 = acc1[mf][nf][1];
            float a2 = acc1[mf][nf][2], a3 = acc1[mf][nf][3];
            float g0 = acc2[mf][nf][0], g1 = acc2[mf][nf][1];
            float g2 = acc2[mf][nf][2], g3 = acc2[mf][nf][3];
            *reinterpret_cast<unsigned*>(C + off0) =
                packh2(a0 / (1.f + __expf(-a0)) * g0, a1 / (1.f + __expf(-a1)) * g1);
            *reinterpret_cast<unsigned*>(C + off1) =
                packh2(a2 / (1.f + __expf(-a2)) * g2, a3 / (1.f + __expf(-a3)) * g3);
        }
    }
}

// ---------------------------------------------------------------------------
// Flash attention fp16, 128-row Q tile, warp tile 16x64 (full row ownership).
// Softmax reduces entirely within warp quads: no cross-warp smem combines.
// K B-frags via non-trans ldmatrix.x4 (pair-along-k); V via ldm_x4_trans.
// grid (T/128, B*H), blockIdx.x reversed (longest-first).
// ---------------------------------------------------------------------------
#define STH_ 72
#define ATTN_SMEM ((128 * STH_ + 2 * 64 * STH_ + 2 * 64 * STH_ + 128 * STH_) * 2)

__global__ void __launch_bounds__(256)
attn_kernel(const __half* __restrict__ Q, const __half* __restrict__ K,
            const __half* __restrict__ V, __half* __restrict__ O)
{
    extern __shared__ char smraw[];
    __half* Qs = reinterpret_cast<__half*>(smraw);          // [128][STH_]
    __half* Ks = Qs + 128 * STH_;                           // [2][64][STH_]
    __half* Vs = Ks + 2 * 64 * STH_;                        // [2][64][STH_]
    __half* Ps = Vs + 2 * 64 * STH_;                        // [128][STH_]

    const int tid  = threadIdx.x;
    const int lane = tid & 31;
    const int warp = tid >> 5;
    const int wm   = warp * 16;          // warp m-offset: 0..112
    const int qm   = lane >> 2;
    const int qk   = lane & 3;

    const int b = blockIdx.y >> 4, h = blockIdx.y & 15;
    const int qi = gridDim.x - 1 - blockIdx.x;   // longest-first
    const int qb = qi * 128;

    const __half* Qb = Q + (size_t)b * T_ * D_ + h * HD_;
    const __half* Kb = K + (size_t)b * T_ * D_ + h * HD_;
    const __half* Vb = V + (size_t)b * T_ * D_ + h * HD_;

    const int lrow = tid >> 2, lch0 = (tid & 3) * 2;
    const int qrow = tid >> 1, qch0 = (tid & 1) * 4;

    auto issue_kv = [&](int j, int s) {
        unsigned kb_ = (unsigned)__cvta_generic_to_shared(&Ks[s * 64 * STH_]);
        unsigned vb_ = (unsigned)__cvta_generic_to_shared(&Vs[s * 64 * STH_]);
        const __half* Kg = Kb + (size_t)(j * 64 + lrow) * D_;
        const __half* Vg = Vb + (size_t)(j * 64 + lrow) * D_;
        #pragma unroll
        for (int i = 0; i < 2; i++) {
            int ch = lch0 + i;
            cp16(kb_ + (unsigned)(lrow * STH_ + ch * 8) * 2, Kg + ch * 8);
            cp16(vb_ + (unsigned)(lrow * STH_ + ch * 8) * 2, Vg + ch * 8);
        }
        CP_COMMIT();
    };

    {
        unsigned qs_ = (unsigned)__cvta_generic_to_shared(Qs);
        const __half* Qg = Qb + (size_t)(qb + qrow) * D_;
        #pragma unroll
        for (int i = 0; i < 4; i++) {
            int ch = qch0 + i;
            cp16(qs_ + (unsigned)(qrow * STH_ + ch * 8) * 2, Qg + ch * 8);
        }
        CP_COMMIT();
    }
    issue_kv(0, 0);
    cp_wait<0>();
    __syncthreads();

    float acc[8][4];
    float m_i[2], l_i[2];
    m_i[0] = m_i[1] = -1e30f;
    l_i[0] = l_i[1] = 0.f;
    #pragma unroll
    for (int nf = 0; nf < 8; nf++)
        #pragma unroll
        for (int c = 0; c < 4; c++) acc[nf][c] = 0.f;

    const int r0l = wm + qm;
    const int ntile = 2 * qi + 2;

    const int lm_lo3  = lane & 7;
    const int lm_hi8  = (lane >> 3) & 1;
    const int lm_colh = lane >> 4;
    const int g_rowo = (lane >> 4) * 8;          // 0 or 8
    const int g_ko   = ((lane >> 3) & 1) * 8;    // 0 or 8

    unsigned qsb = (unsigned)__cvta_generic_to_shared(Qs);
    unsigned psb = (unsigned)__cvta_generic_to_shared(Ps);

    for (int j = 0; j < ntile; j++) {
        const int s = j & 1;
        if (j + 1 < ntile) issue_kv(j + 1, s ^ 1);

        unsigned ksb = (unsigned)__cvta_generic_to_shared(&Ks[s * 64 * STH_]);
        unsigned vsb = (unsigned)__cvta_generic_to_shared(&Vs[s * 64 * STH_]);

        // ---- S = Q @ K^T ----
        float sv[8][4];
        #pragma unroll
        for (int nf = 0; nf < 8; nf++)
            #pragma unroll
            for (int c = 0; c < 4; c++) sv[nf][c] = 0.f;

        #pragma unroll
        for (int ks = 0; ks < 4; ks++) {
            const int kk = ks * 16;
            unsigned a0, a1, a2, a3;
            {
                int m = wm + lm_hi8 * 8 + lm_lo3;
                ldm_x4(a0, a1, a2, a3, qsb + (unsigned)(m * STH_ + kk + lm_colh * 8) * 2);
            }
            #pragma unroll
            for (int ng = 0; ng < 4; ng++) {
                int n0 = ng * 16;
                unsigned addr = ksb + (unsigned)((n0 + g_rowo + lm_lo3) * STH_ + kk + g_ko) * 2;
                unsigned b0a, b1a, b0b, b1b;
                ldm_x4(b0a, b1a, b0b, b1b, addr);
                mma_f16(sv[2 * ng],     a0, a1, a2, a3, b0a, b1a);
                mma_f16(sv[2 * ng + 1], a0, a1, a2, a3, b0b, b1b);
            }
        }

        const int jb = j * 64;
        const bool needmask = (jb >= qb);
        #pragma unroll
        for (int nf = 0; nf < 8; nf++) {
            int colb = nf * 8 + 2 * qk;
            #pragma unroll
            for (int c = 0; c < 4; c++) {
                int colg = jb + colb + (c & 1);
                int rowg = qb + r0l + ((c >> 1) ? 8 : 0);
                float v = sv[nf][c] * 0.125f;
                if (needmask && (colg > rowg)) v = -1e30f;
                sv[nf][c] = v;
            }
        }

        float mx0 = -1e30f, mx1 = -1e30f;
        #pragma unroll
        for (int nf = 0; nf < 8; nf++) {
            mx0 = fmaxf(mx0, fmaxf(sv[nf][0], sv[nf][1]));
            mx1 = fmaxf(mx1, fmaxf(sv[nf][2], sv[nf][3]));
        }
        #pragma unroll
        for (int o = 1; o < 4; o <<= 1) {
            mx0 = fmaxf(mx0, __shfl_xor_sync(0xffffffffu, mx0, o));
            mx1 = fmaxf(mx1, __shfl_xor_sync(0xffffffffu, mx1, o));
        }
        float mn0 = fmaxf(m_i[0], mx0);
        float mn1 = fmaxf(m_i[1], mx1);

        float sum0 = 0.f, sum1 = 0.f;
        #pragma unroll
        for (int nf = 0; nf < 8; nf++) {
            int colb = nf * 8 + 2 * qk;
            float p0 = __expf(sv[nf][0] - mn0);
            float p1 = __expf(sv[nf][1] - mn0);
            float p2 = __expf(sv[nf][2] - mn1);
            float p3 = __expf(sv[nf][3] - mn1);
            sum0 += p0 + p1;
            sum1 += p2 + p3;
            *reinterpret_cast<unsigned*>(&Ps[(size_t)r0l * STH_ + colb])       = packh2(p0, p1);
            *reinterpret_cast<unsigned*>(&Ps[(size_t)(r0l + 8) * STH_ + colb]) = packh2(p2, p3);
        }
        #pragma unroll
        for (int o = 1; o < 4; o <<= 1) {
            sum0 += __shfl_xor_sync(0xffffffffu, sum0, o);
            sum1 += __shfl_xor_sync(0xffffffffu, sum1, o);
        }

        float al0 = __expf(m_i[0] - mn0);
        float al1 = __expf(m_i[1] - mn1);
        l_i[0] = l_i[0] * al0 + sum0;  m_i[0] = mn0;
        l_i[1] = l_i[1] * al1 + sum1;  m_i[1] = mn1;
        #pragma unroll
        for (int nf = 0; nf < 8; nf++) {
            acc[nf][0] *= al0; acc[nf][1] *= al0;
            acc[nf][2] *= al1; acc[nf][3] *= al1;
        }

        __syncwarp();

        // ---- O += P @ V ----
        #pragma unroll
        for (int ks = 0; ks < 4; ks++) {
            const int kk = ks * 16;
            unsigned a0, a1, a2, a3;
            {
                int m = wm + lm_hi8 * 8 + lm_lo3;
                ldm_x4(a0, a1, a2, a3, psb + (unsigned)(m * STH_ + kk + lm_colh * 8) * 2);
            }
            #pragma unroll
            for (int nb = 0; nb < 4; nb++) {
                int vrow = kk + lm_hi8 * 8 + lm_lo3;
                int vcol = nb * 16 + lm_colh * 8;
                unsigned addr = vsb + (unsigned)(vrow * STH_ + vcol) * 2;
                unsigned r0, r1, r2, r3;
                ldm_x4_trans(r0, r1, r2, r3, addr);
                mma_f16(acc[2 * nb],     a0, a1, a2, a3, r0, r1);
                mma_f16(acc[2 * nb + 1], a0, a1, a2, a3, r2, r3);
            }
        }

        if (j + 1 < ntile) cp_wait<0>();
        __syncthreads();
    }

    {
        float inv0 = 1.0f / l_i[0], inv1 = 1.0f / l_i[1];
        #pragma unroll
        for (int nf = 0; nf < 8; nf++) {
            int col = h * HD_ + nf * 8 + 2 * qk;
            size_t off0 = (size_t)b * T_ * D_ + (size_t)(qb + r0l) * D_ + col;
            size_t off1 = (size_t)b * T_ * D_ + (size_t)(qb + r0l + 8) * D_ + col;
            *reinterpret_cast<unsigned*>(O + off0) = packh2(acc[nf][0] * inv0, acc[nf][1] * inv0);
            *reinterpret_cast<unsigned*>(O + off1) = packh2(acc[nf][2] * inv1, acc[nf][3] * inv1);
        }
    }
}

// ---------------------------------------------------------------------------
// Orchestration
// ---------------------------------------------------------------------------
extern "C" void kernel_launch(void* const* d_in, const int* in_sizes, int n_in,
                              void* d_out, int out_size)
{
    const float* h    = (const float*)d_in[0];
    const float* alng = (const float*)d_in[2];
    const float* alnb = (const float*)d_in[3];
    const float* mlng = (const float*)d_in[4];
    const float* mlnb = (const float*)d_in[5];
    const float* wq   = (const float*)d_in[6];
    const float* wk   = (const float*)d_in[7];
    const float* wv   = (const float*)d_in[8];
    const float* wo   = (const float*)d_in[9];
    const float* w1   = (const float*)d_in[10];
    const float* w2   = (const float*)d_in[11];
    const float* wout = (const float*)d_in[12];
    float* out = (float*)d_out;

    __half *px, *pq, *pk, *pv, *po, *py, *pa;
    float *ph2;
    __half *pwq, *pwk, *pwv, *pwo, *pw1, *pw2, *pwout;
    cudaGetSymbolAddress((void**)&px,  g_x);
    cudaGetSymbolAddress((void**)&pq,  g_q);
    cudaGetSymbolAddress((void**)&pk,  g_k);
    cudaGetSymbolAddress((void**)&pv,  g_v);
    cudaGetSymbolAddress((void**)&po,  g_o);
    cudaGetSymbolAddress((void**)&ph2, g_h2);
    cudaGetSymbolAddress((void**)&py,  g_y);
    cudaGetSymbolAddress((void**)&pa,  g_a);
    cudaGetSymbolAddress((void**)&pwq,   g_wq);
    cudaGetSymbolAddress((void**)&pwk,   g_wk);
    cudaGetSymbolAddress((void**)&pwv,   g_wv);
    cudaGetSymbolAddress((void**)&pwo,   g_wo);
    cudaGetSymbolAddress((void**)&pw1,   g_w1);
    cudaGetSymbolAddress((void**)&pw2,   g_w2);
    cudaGetSymbolAddress((void**)&pwout, g_wout);

    cudaFuncSetAttribute(attn_kernel, cudaFuncAttributeMaxDynamicSharedMemorySize, ATTN_SMEM);
    cudaFuncSetAttribute(ffn_kernel,  cudaFuncAttributeMaxDynamicSharedMemorySize, GEMM_SMEM);
    cudaFuncSetAttribute(tgemm_kernel<false, true, 3>, cudaFuncAttributeMaxDynamicSharedMemorySize, GEMM_SMEM);
    cudaFuncSetAttribute(tgemm_kernel<true, false, 1>, cudaFuncAttributeMaxDynamicSharedMemorySize, GEMM_SMEM);

    // all weights -> fp16 in ONE launch
    PackArgs pargs;
    pargs.src[0] = wq;   pargs.dst[0] = pwq;
    pargs.src[1] = wk;   pargs.dst[1] = pwk;
    pargs.src[2] = wv;   pargs.dst[2] = pwv;
    pargs.src[3] = wo;   pargs.dst[3] = pwo;
    pargs.src[4] = w1;   pargs.dst[4] = pw1;
    pargs.src[5] = w2;   pargs.dst[5] = pw2;
    pargs.src[6] = wout; pargs.dst[6] = pwout;
    packall_kernel<<<2097152 / 256, 256>>>(pargs);

    dim3 gQKV(D_ / 128, ROWS_ / 128, 3);    // (8, 64, 3)
    dim3 gD(D_ / 128, ROWS_ / 128);         // (8, 64)
    dim3 gFFN(FFN_ / 64, ROWS_ / 128);      // (64, 64)

    // x = fp16(LN(h))
    ln_kernel<<<ROWS_, 256>>>(h, alng, alnb, px);
    // q,k,v = fp16(x @ {wq,wk,wv})
    tgemm_kernel<false, true, 3><<<gQKV, 256, GEMM_SMEM>>>(px, pwq, pwk, pwv, nullptr,
                                                           pq, pk, pv, ROWS_, D_, D_);
    // o = fp16(attention(q,k,v))  -- 128-row Q tiles
    attn_kernel<<<dim3(T_ / 128, B_ * H_), 256, ATTN_SMEM>>>(pq, pk, pv, po);
    // h2 = h + o @ wo   (fp32)
    tgemm_kernel<true, false, 1><<<gD, 256, GEMM_SMEM>>>(po, pwo, nullptr, nullptr, h,
                                                         ph2, nullptr, nullptr, ROWS_, D_, D_);
    // y = fp16(LN(h2))
    ln_kernel<<<ROWS_, 256>>>(ph2, mlng, mlnb, py);
    // a = fp16(silu(y@w1) * (y@w2))
    ffn_kernel<<<gFFN, 256, GEMM_SMEM>>>(py, pw1, pw2, pa, ROWS_, FFN_, D_);
    // out = h2 + a @ wout   (fp32)
    tgemm_kernel<true, false, 1><<<gD, 256, GEMM_SMEM>>>(pa, pwout, nullptr, nullptr, ph2,
                                                         out, nullptr, nullptr, ROWS_, D_, FFN_);
}